// round 12
// baseline (speedup 1.0000x reference)
#include <cuda_runtime.h>
#include <cuda_bf16.h>
#include <cstdint>

#define BB 8
#define NN 2048
#define DD 256
#define K3 768            // 3-term split K' = 3*DD (bf16)
#define KK 100
#define RR 5
#define BIGV 1000000000.0f
#define LN_EPS 1e-5f
#define ESHIFT 48.0f

// GEMM tiling
#define BM 128
#define BN 128
#define BKE 64                         // bf16 elems per stage (128 B/row)
#define PADB 72                        // padded row stride in bf16 elems
#define STAGE_H (2 * BM * PADB)        // halves per stage (A+B) = 18432
#define NSTG 3
#define SMEM_BYTES (NSTG * STAGE_H * 2)   // 110592
#define NCB (NN / BN)                  // 16 column blocks

// ---- scratch (device globals; no allocations allowed) ----
__device__ __align__(128) __nv_bfloat16 g_qsb[(size_t)BB * NN * K3];
__device__ __align__(128) __nv_bfloat16 g_ksb[(size_t)BB * NN * K3];
__device__ __align__(128) float g_partial[(size_t)NCB * BB * NN];
__device__ float g_rinv[BB * NN];
__device__ float g_diag[BB * NN];
__device__ int   g_sel[BB * NN];
__device__ int   g_topidx[BB * KK];
__device__ int   g_pairs[BB * KK * RR * 2];

// ============================================================
// helpers
// ============================================================
__device__ __forceinline__ void ldsm4(unsigned& r0, unsigned& r1, unsigned& r2, unsigned& r3,
                                      unsigned addr) {
    asm volatile("ldmatrix.sync.aligned.m8n8.x4.shared.b16 {%0,%1,%2,%3}, [%4];"
                 : "=r"(r0), "=r"(r1), "=r"(r2), "=r"(r3) : "r"(addr));
}
__device__ __forceinline__ void mma_bf16(float* d, const unsigned* a, const unsigned* b) {
    asm volatile("mma.sync.aligned.m16n8k16.row.col.f32.bf16.bf16.f32 "
                 "{%0,%1,%2,%3},{%4,%5,%6,%7},{%8,%9},{%0,%1,%2,%3};"
                 : "+f"(d[0]), "+f"(d[1]), "+f"(d[2]), "+f"(d[3])
                 : "r"(a[0]), "r"(a[1]), "r"(a[2]), "r"(a[3]), "r"(b[0]), "r"(b[1]));
}
__device__ __forceinline__ void cpa16(void* smem_dst, const void* gsrc) {
    unsigned d = (unsigned)__cvta_generic_to_shared(smem_dst);
    asm volatile("cp.async.cg.shared.global [%0], [%1], 16;" :: "r"(d), "l"(gsrc));
}

// ============================================================
// Kernel 0: bf16 3-term split.  q -> [qh,qh,ql] ; k -> [kh,kl,kh]
// ============================================================
__global__ __launch_bounds__(256) void split3b_kernel(
    const float* __restrict__ q, const float* __restrict__ k)
{
    const bool isK = blockIdx.y != 0;
    const float4* src = (const float4*)(isK ? k : q);
    __nv_bfloat16* dst = isK ? g_ksb : g_qsb;
    size_t i = (size_t)blockIdx.x * 256 + threadIdx.x;

    float4 v0 = src[2 * i];
    float4 v1 = src[2 * i + 1];
    float xs[8] = {v0.x, v0.y, v0.z, v0.w, v1.x, v1.y, v1.z, v1.w};

    __align__(16) __nv_bfloat16 out[24];
#pragma unroll
    for (int e = 0; e < 8; e++) {
        __nv_bfloat16 h = __float2bfloat16(xs[e]);
        __nv_bfloat16 l = __float2bfloat16(xs[e] - __bfloat162float(h));
        if (!isK) { out[3 * e] = h; out[3 * e + 1] = h; out[3 * e + 2] = l; }
        else      { out[3 * e] = h; out[3 * e + 1] = l; out[3 * e + 2] = h; }
    }
    uint4* o = (uint4*)(dst + 24 * i);
    o[0] = ((uint4*)out)[0];
    o[1] = ((uint4*)out)[1];
    o[2] = ((uint4*)out)[2];
}

// ============================================================
// Kernel 1: bf16 GEMM; epilogue writes exp(logit-ESHIFT) and
// deterministic per-row partial sums for this 128-col block.
// ============================================================
__global__ __launch_bounds__(256, 2) void gemm_bf16k(
    const __nv_bfloat16* __restrict__ A0, const __nv_bfloat16* __restrict__ B0,
    float* __restrict__ out)
{
    extern __shared__ __nv_bfloat16 sm[];
    const int b = blockIdx.z;
    const int row0 = blockIdx.y * BM;
    const int col0 = blockIdx.x * BN;
    const __nv_bfloat16* A  = A0 + (size_t)b * NN * K3;
    const __nv_bfloat16* Bm = B0 + (size_t)b * NN * K3;
    float* C = out + (size_t)b * NN * NN;

    const int tid = threadIdx.x;
    const int warp = tid >> 5, lane = tid & 31;
    const int wm = (warp >> 2) * 64;
    const int wn = (warp & 3) * 32;

    float acc[4][4][4];
#pragma unroll
    for (int mf = 0; mf < 4; mf++)
#pragma unroll
        for (int nf = 0; nf < 4; nf++)
#pragma unroll
            for (int e = 0; e < 4; e++) acc[mf][nf][e] = 0.0f;

#define LOAD_STAGE(s, kt)                                                      \
    do {                                                                       \
        __nv_bfloat16* As_ = sm + (s) * STAGE_H;                               \
        __nv_bfloat16* Bs_ = As_ + BM * PADB;                                  \
        _Pragma("unroll")                                                      \
        for (int l = 0; l < 4; l++) {                                          \
            int idx = tid + l * 256;                                           \
            int row = idx >> 3;                                                \
            int ce  = (idx & 7) * 8;                                           \
            cpa16(&As_[row * PADB + ce], &A [(size_t)(row0 + row) * K3 + (kt) + ce]); \
            cpa16(&Bs_[row * PADB + ce], &Bm[(size_t)(col0 + row) * K3 + (kt) + ce]); \
        }                                                                      \
        asm volatile("cp.async.commit_group;");                                \
    } while (0)

    LOAD_STAGE(0, 0);
    LOAD_STAGE(1, BKE);

    const int NT = K3 / BKE;   // 12
    int cur = 0, nxt = 2;
    for (int t = 0; t < NT; t++) {
        if (t < NT - 1) { asm volatile("cp.async.wait_group 1;"); }
        else            { asm volatile("cp.async.wait_group 0;"); }
        __syncthreads();

        if (t + 2 < NT) {
            LOAD_STAGE(nxt, (t + 2) * BKE);
        }

        const __nv_bfloat16* As_ = sm + cur * STAGE_H;
        const __nv_bfloat16* Bs_ = As_ + BM * PADB;

#pragma unroll
        for (int kk = 0; kk < 4; kk++) {
            const int kb = kk * 16;

            unsigned a[4][4];
#pragma unroll
            for (int mf = 0; mf < 4; mf++) {
                int arow = wm + mf * 16 + (lane & 15);
                int acol = kb + ((lane >> 4) << 3);
                unsigned addr = (unsigned)__cvta_generic_to_shared(&As_[arow * PADB + acol]);
                ldsm4(a[mf][0], a[mf][1], a[mf][2], a[mf][3], addr);
            }
            unsigned bf[4][2];
#pragma unroll
            for (int half = 0; half < 2; half++) {
                int brow = wn + half * 16 + (lane & 7) + ((lane >> 4) << 3);
                int bcol = kb + (((lane >> 3) & 1) << 3);
                unsigned addr = (unsigned)__cvta_generic_to_shared(&Bs_[brow * PADB + bcol]);
                ldsm4(bf[half * 2][0], bf[half * 2][1],
                      bf[half * 2 + 1][0], bf[half * 2 + 1][1], addr);
            }
#pragma unroll
            for (int mf = 0; mf < 4; mf++)
#pragma unroll
                for (int nf = 0; nf < 4; nf++)
                    mma_bf16(acc[mf][nf], a[mf], bf[nf]);
        }

        cur = (cur == 2) ? 0 : cur + 1;
        nxt = (nxt == 2) ? 0 : nxt + 1;
    }
#undef LOAD_STAGE

    // ---- epilogue: exp + store + deterministic partial row sums ----
    float ps[4][2];
#pragma unroll
    for (int mf = 0; mf < 4; mf++) { ps[mf][0] = 0.0f; ps[mf][1] = 0.0f; }

#pragma unroll
    for (int mf = 0; mf < 4; mf++)
#pragma unroll
        for (int nf = 0; nf < 4; nf++) {
            int r0 = row0 + wm + mf * 16 + (lane >> 2);
            int c0 = col0 + wn + nf * 8 + (lane & 3) * 2;
            float e0 = __expf(acc[mf][nf][0] - ESHIFT);
            float e1 = __expf(acc[mf][nf][1] - ESHIFT);
            float e2 = __expf(acc[mf][nf][2] - ESHIFT);
            float e3 = __expf(acc[mf][nf][3] - ESHIFT);
            *(float2*)&C[(size_t)r0 * NN + c0]       = make_float2(e0, e1);
            *(float2*)&C[(size_t)(r0 + 8) * NN + c0] = make_float2(e2, e3);
            ps[mf][0] += e0 + e1;
            ps[mf][1] += e2 + e3;
        }

    // quad reduce: lanes sharing (lane>>2) hold same rows, differ in cols
#pragma unroll
    for (int mf = 0; mf < 4; mf++)
#pragma unroll
        for (int h = 0; h < 2; h++) {
            float v = ps[mf][h];
            v += __shfl_xor_sync(0xffffffffu, v, 1);
            v += __shfl_xor_sync(0xffffffffu, v, 2);
            ps[mf][h] = v;
        }

    __syncthreads();                 // smem no longer needed for tiles
    float* rs = (float*)sm;          // [4 warp-cols][128 rows]
    if ((lane & 3) == 0) {
#pragma unroll
        for (int mf = 0; mf < 4; mf++)
#pragma unroll
            for (int h = 0; h < 2; h++) {
                int rl = wm + mf * 16 + h * 8 + (lane >> 2);
                rs[(warp & 3) * BM + rl] = ps[mf][h];
            }
    }
    __syncthreads();
    if (tid < BM) {
        float tot = rs[tid] + rs[BM + tid] + rs[2 * BM + tid] + rs[3 * BM + tid];
        g_partial[(size_t)blockIdx.x * (BB * NN) + b * NN + row0 + tid] = tot;
    }
}

// ============================================================
// Kernel 2a: reciprocal row sums (16 partials per row)
// ============================================================
__global__ __launch_bounds__(256) void rowsum_kernel()
{
    const int r = blockIdx.x * 256 + threadIdx.x;   // 0 .. BB*NN-1
    float s = 0.0f;
#pragma unroll
    for (int c = 0; c < NCB; c++) s += g_partial[(size_t)c * (BB * NN) + r];
    g_rinv[r] = 1.0f / s;
}

// ============================================================
// Kernel 2b: normalize (pure stream) + diag extract
// one block per row, 256 thr x 2 float4
// ============================================================
__global__ __launch_bounds__(256) void normalize_kernel(float* __restrict__ scores)
{
    const int rowg = blockIdx.x;
    const int i    = rowg & (NN - 1);
    float* row = scores + (size_t)rowg * NN;
    const int t = threadIdx.x;
    const float inv = g_rinv[rowg];

    float4 v0 = ((float4*)row)[t];
    float4 v1 = ((float4*)row)[t + 256];

    v0.x *= inv; v0.y *= inv; v0.z *= inv; v0.w *= inv;
    v1.x *= inv; v1.y *= inv; v1.z *= inv; v1.w *= inv;

    ((float4*)row)[t]       = v0;
    ((float4*)row)[t + 256] = v1;

    int c0 = i >> 2, cc = i & 3;
    if (c0 == t) {
        float d = (cc == 0) ? v0.x : (cc == 1) ? v0.y : (cc == 2) ? v0.z : v0.w;
        g_diag[rowg] = d;
    } else if (c0 == t + 256) {
        float d = (cc == 0) ? v1.x : (cc == 1) ? v1.y : (cc == 2) ? v1.z : v1.w;
        g_diag[rowg] = d;
    }
}

// ============================================================
// Kernel 3a: rank counting — one WARP per element
// ============================================================
__global__ __launch_bounds__(256) void topk_count_kernel()
{
    const int b = blockIdx.y;
    __shared__ __align__(16) float v[NN];

    for (int i = threadIdx.x; i < NN / 4; i += 256)
        ((float4*)v)[i] = ((const float4*)(g_diag + b * NN))[i];
    __syncthreads();

    const int warp = threadIdx.x >> 5;
    const int lane = threadIdx.x & 31;
    const int i = blockIdx.x * 8 + warp;
    const float vi = v[i];

    int cnt = 0;
#pragma unroll 4
    for (int j4 = lane; j4 < NN / 4; j4 += 32) {
        float4 w = ((const float4*)v)[j4];
        int j = j4 * 4;
        cnt += (w.x > vi) || ((w.x == vi) && (j + 0 < i));
        cnt += (w.y > vi) || ((w.y == vi) && (j + 1 < i));
        cnt += (w.z > vi) || ((w.z == vi) && (j + 2 < i));
        cnt += (w.w > vi) || ((w.w == vi) && (j + 3 < i));
    }
#pragma unroll
    for (int o = 16; o > 0; o >>= 1) cnt += __shfl_xor_sync(0xffffffffu, cnt, o);

    if (lane == 0) g_sel[b * NN + i] = (cnt < KK) ? 1 : 0;
}

// ============================================================
// Kernel 3b: compaction via block scan
// ============================================================
__global__ __launch_bounds__(1024) void topk_compact_kernel()
{
    const int b = blockIdx.x;
    const int t = threadIdx.x;
    __shared__ int wsum[32];

    const int f0 = g_sel[b * NN + 2 * t];
    const int f1 = g_sel[b * NN + 2 * t + 1];
    const int mysum = f0 + f1;

    int inc = mysum;
#pragma unroll
    for (int o = 1; o < 32; o <<= 1) {
        int u = __shfl_up_sync(0xffffffffu, inc, o);
        if ((t & 31) >= o) inc += u;
    }
    if ((t & 31) == 31) wsum[t >> 5] = inc;
    __syncthreads();
    if (t < 32) {
        int wv = wsum[t];
#pragma unroll
        for (int o = 1; o < 32; o <<= 1) {
            int u = __shfl_up_sync(0xffffffffu, wv, o);
            if (t >= o) wv += u;
        }
        wsum[t] = wv;
    }
    __syncthreads();

    int excl = inc - mysum + ((t >> 5) ? wsum[(t >> 5) - 1] : 0);
    if (f0 && excl < KK)      g_topidx[b * KK + excl] = 2 * t;
    if (f1 && excl + f0 < KK) g_topidx[b * KK + excl + f0] = 2 * t + 1;
}

// ============================================================
// Kernel 4: rel top-R + soi triples; fully parallel scatter
// ============================================================
__global__ __launch_bounds__(128) void rel_kernel(
    const float* __restrict__ scores, float* __restrict__ soi_out)
{
    const int b  = blockIdx.y;
    const int tI = blockIdx.x;
    __shared__ float r[KK];
    __shared__ unsigned char sel[KK];

    const int ti = g_topidx[b * KK + tI];
    const int t  = threadIdx.x;

    if (t < KK) {
        int tj = g_topidx[b * KK + t];
        float val = scores[((size_t)b * NN + ti) * NN + tj];
        r[t] = (t == tI) ? BIGV : val;
    }
    __syncthreads();

    if (t < KK) {
        float vi = r[t];
        int cnt = 0;
#pragma unroll 4
        for (int j = 0; j < KK; j++) {
            float vj = r[j];
            cnt += (vj > vi) || ((vj == vi) && (j < t));
        }
        sel[t] = (cnt < RR) ? 1 : 0;
    }
    __syncthreads();

    if (t < KK && sel[t]) {
        int pos = 0;
#pragma unroll 4
        for (int j = 0; j < KK; j++) pos += (j < t) ? sel[j] : 0;
        if (pos < RR) {
            int obj = g_topidx[b * KK + t];
            int p = (b * KK + tI) * RR + pos;
            g_pairs[2 * p]     = ti;
            g_pairs[2 * p + 1] = obj;
            size_t so = (size_t)p * 3;
            soi_out[so + 0] = (float)b;
            soi_out[so + 1] = (float)ti;
            soi_out[so + 2] = (float)obj;
        }
    }
}

// ============================================================
// Kernel 5: re = LayerNorm(q[b,subj] + q[b,obj])
// ============================================================
__global__ __launch_bounds__(256) void re_kernel(
    const float* __restrict__ q, float* __restrict__ re_out)
{
    const int warp = threadIdx.x >> 5;
    const int lane = threadIdx.x & 31;
    const int p = blockIdx.x * 8 + warp;
    if (p >= BB * KK * RR) return;

    const int b = p / (KK * RR);
    const int subj = g_pairs[2 * p];
    const int obj  = g_pairs[2 * p + 1];
    const float4* qs = (const float4*)(q + ((size_t)b * NN + subj) * DD);
    const float4* qo = (const float4*)(q + ((size_t)b * NN + obj)  * DD);

    float x[8];
    float s = 0.0f, s2 = 0.0f;
#pragma unroll
    for (int c = 0; c < 2; c++) {
        float4 a = qs[lane + 32 * c];
        float4 o = qo[lane + 32 * c];
        x[4 * c + 0] = a.x + o.x; x[4 * c + 1] = a.y + o.y;
        x[4 * c + 2] = a.z + o.z; x[4 * c + 3] = a.w + o.w;
    }
#pragma unroll
    for (int e = 0; e < 8; e++) { s += x[e]; s2 += x[e] * x[e]; }
#pragma unroll
    for (int o = 16; o > 0; o >>= 1) {
        s  += __shfl_xor_sync(0xffffffffu, s,  o);
        s2 += __shfl_xor_sync(0xffffffffu, s2, o);
    }
    const float mu  = s * (1.0f / DD);
    const float var = s2 * (1.0f / DD) - mu * mu;
    const float inv = rsqrtf(var + LN_EPS);

    float4* dst = (float4*)(re_out + (size_t)p * DD);
#pragma unroll
    for (int c = 0; c < 2; c++) {
        float4 r;
        r.x = (x[4 * c + 0] - mu) * inv;
        r.y = (x[4 * c + 1] - mu) * inv;
        r.z = (x[4 * c + 2] - mu) * inv;
        r.w = (x[4 * c + 3] - mu) * inv;
        dst[lane + 32 * c] = r;
    }
}

// ============================================================
extern "C" void kernel_launch(void* const* d_in, const int* in_sizes, int n_in,
                              void* d_out, int out_size)
{
    const float* q = (const float*)d_in[0];
    const float* k = (const float*)d_in[1];

    float* scores = (float*)d_out;
    float* soi    = scores + (size_t)BB * NN * NN;
    float* re     = soi + (size_t)BB * KK * RR * 3;

    void *qs_ptr = nullptr, *ks_ptr = nullptr;
    cudaGetSymbolAddress(&qs_ptr, g_qsb);
    cudaGetSymbolAddress(&ks_ptr, g_ksb);

    cudaFuncSetAttribute(gemm_bf16k, cudaFuncAttributeMaxDynamicSharedMemorySize, SMEM_BYTES);

    split3b_kernel<<<dim3(BB * NN * DD / 8 / 256, 2), 256>>>(q, k);
    gemm_bf16k<<<dim3(NN / BN, NN / BM, BB), 256, SMEM_BYTES>>>(
        (const __nv_bfloat16*)qs_ptr, (const __nv_bfloat16*)ks_ptr, scores);
    rowsum_kernel<<<BB * NN / 256, 256>>>();
    normalize_kernel<<<BB * NN, 256>>>(scores);
    topk_count_kernel<<<dim3(NN / 8, BB), 256>>>();
    topk_compact_kernel<<<BB, 1024>>>();
    rel_kernel<<<dim3(KK, BB), 128>>>(scores, soi);
    re_kernel<<<(BB * KK * RR + 7) / 8, 256>>>(q, re);
}

// round 13
// speedup vs baseline: 1.0347x; 1.0347x over previous
#include <cuda_runtime.h>
#include <cuda_bf16.h>
#include <cstdint>

#define BB 8
#define NN 2048
#define DD 256
#define K3 768            // 3-term split K' = 3*DD (bf16)
#define KK 100
#define RR 5
#define BIGV 1000000000.0f
#define LN_EPS 1e-5f
#define ESHIFT 48.0f

// GEMM tiling
#define BM 128
#define BN 128
#define BKE 64                         // bf16 elems per stage (128 B/row)
#define PADB 72                        // padded row stride in bf16 elems
#define STAGE_H (2 * BM * PADB)        // halves per stage (A+B) = 18432
#define NSTG 3
#define SMEM_BYTES (NSTG * STAGE_H * 2)   // 110592

// ---- scratch (device globals; no allocations allowed) ----
__device__ __align__(128) __nv_bfloat16 g_qsb[(size_t)BB * NN * K3];
__device__ __align__(128) __nv_bfloat16 g_ksb[(size_t)BB * NN * K3];
__device__ float g_diag[BB * NN];
__device__ int   g_sel[BB * NN];
__device__ int   g_topidx[BB * KK];
__device__ int   g_pairs[BB * KK * RR * 2];

// ============================================================
// helpers
// ============================================================
__device__ __forceinline__ void ldsm4(unsigned& r0, unsigned& r1, unsigned& r2, unsigned& r3,
                                      unsigned addr) {
    asm volatile("ldmatrix.sync.aligned.m8n8.x4.shared.b16 {%0,%1,%2,%3}, [%4];"
                 : "=r"(r0), "=r"(r1), "=r"(r2), "=r"(r3) : "r"(addr));
}
__device__ __forceinline__ void mma_bf16(float* d, const unsigned* a, const unsigned* b) {
    asm volatile("mma.sync.aligned.m16n8k16.row.col.f32.bf16.bf16.f32 "
                 "{%0,%1,%2,%3},{%4,%5,%6,%7},{%8,%9},{%0,%1,%2,%3};"
                 : "+f"(d[0]), "+f"(d[1]), "+f"(d[2]), "+f"(d[3])
                 : "r"(a[0]), "r"(a[1]), "r"(a[2]), "r"(a[3]), "r"(b[0]), "r"(b[1]));
}
__device__ __forceinline__ void cpa16(void* smem_dst, const void* gsrc) {
    unsigned d = (unsigned)__cvta_generic_to_shared(smem_dst);
    asm volatile("cp.async.cg.shared.global [%0], [%1], 16;" :: "r"(d), "l"(gsrc));
}

// ============================================================
// Kernel 0: bf16 3-term split.  q -> [qh,qh,ql] ; k -> [kh,kl,kh]
// ============================================================
__global__ __launch_bounds__(256) void split3b_kernel(
    const float* __restrict__ q, const float* __restrict__ k)
{
    const bool isK = blockIdx.y != 0;
    const float4* src = (const float4*)(isK ? k : q);
    __nv_bfloat16* dst = isK ? g_ksb : g_qsb;
    size_t i = (size_t)blockIdx.x * 256 + threadIdx.x;

    float4 v0 = src[2 * i];
    float4 v1 = src[2 * i + 1];
    float xs[8] = {v0.x, v0.y, v0.z, v0.w, v1.x, v1.y, v1.z, v1.w};

    __align__(16) __nv_bfloat16 out[24];
#pragma unroll
    for (int e = 0; e < 8; e++) {
        __nv_bfloat16 h = __float2bfloat16(xs[e]);
        __nv_bfloat16 l = __float2bfloat16(xs[e] - __bfloat162float(h));
        if (!isK) { out[3 * e] = h; out[3 * e + 1] = h; out[3 * e + 2] = l; }
        else      { out[3 * e] = h; out[3 * e + 1] = l; out[3 * e + 2] = h; }
    }
    uint4* o = (uint4*)(dst + 24 * i);
    o[0] = ((uint4*)out)[0];
    o[1] = ((uint4*)out)[1];
    o[2] = ((uint4*)out)[2];
}

// ============================================================
// Kernel 1: bf16 mma.sync m16n8k16 GEMM over K'=768
// 3-stage cp.async pipeline, ONE __syncthreads per iteration
// ============================================================
__global__ __launch_bounds__(256, 2) void gemm_bf16k(
    const __nv_bfloat16* __restrict__ A0, const __nv_bfloat16* __restrict__ B0,
    float* __restrict__ out)
{
    extern __shared__ __nv_bfloat16 sm[];
    const int b = blockIdx.z;
    const int row0 = blockIdx.y * BM;
    const int col0 = blockIdx.x * BN;
    const __nv_bfloat16* A  = A0 + (size_t)b * NN * K3;
    const __nv_bfloat16* Bm = B0 + (size_t)b * NN * K3;
    float* C = out + (size_t)b * NN * NN;

    const int tid = threadIdx.x;
    const int warp = tid >> 5, lane = tid & 31;
    const int wm = (warp >> 2) * 64;
    const int wn = (warp & 3) * 32;

    float acc[4][4][4];
#pragma unroll
    for (int mf = 0; mf < 4; mf++)
#pragma unroll
        for (int nf = 0; nf < 4; nf++)
#pragma unroll
            for (int e = 0; e < 4; e++) acc[mf][nf][e] = 0.0f;

#define LOAD_STAGE(s, kt)                                                      \
    do {                                                                       \
        __nv_bfloat16* As_ = sm + (s) * STAGE_H;                               \
        __nv_bfloat16* Bs_ = As_ + BM * PADB;                                  \
        _Pragma("unroll")                                                      \
        for (int l = 0; l < 4; l++) {                                          \
            int idx = tid + l * 256;                                           \
            int row = idx >> 3;                                                \
            int ce  = (idx & 7) * 8;                                           \
            cpa16(&As_[row * PADB + ce], &A [(size_t)(row0 + row) * K3 + (kt) + ce]); \
            cpa16(&Bs_[row * PADB + ce], &Bm[(size_t)(col0 + row) * K3 + (kt) + ce]); \
        }                                                                      \
        asm volatile("cp.async.commit_group;");                                \
    } while (0)

    LOAD_STAGE(0, 0);
    LOAD_STAGE(1, BKE);

    const int NT = K3 / BKE;   // 12
    int cur = 0, nxt = 2;
    for (int t = 0; t < NT; t++) {
        if (t < NT - 1) { asm volatile("cp.async.wait_group 1;"); }
        else            { asm volatile("cp.async.wait_group 0;"); }
        __syncthreads();

        if (t + 2 < NT) {
            LOAD_STAGE(nxt, (t + 2) * BKE);
        }

        const __nv_bfloat16* As_ = sm + cur * STAGE_H;
        const __nv_bfloat16* Bs_ = As_ + BM * PADB;

#pragma unroll
        for (int kk = 0; kk < 4; kk++) {
            const int kb = kk * 16;

            unsigned a[4][4];
#pragma unroll
            for (int mf = 0; mf < 4; mf++) {
                int arow = wm + mf * 16 + (lane & 15);
                int acol = kb + ((lane >> 4) << 3);
                unsigned addr = (unsigned)__cvta_generic_to_shared(&As_[arow * PADB + acol]);
                ldsm4(a[mf][0], a[mf][1], a[mf][2], a[mf][3], addr);
            }
            unsigned bf[4][2];
#pragma unroll
            for (int half = 0; half < 2; half++) {
                int brow = wn + half * 16 + (lane & 7) + ((lane >> 4) << 3);
                int bcol = kb + (((lane >> 3) & 1) << 3);
                unsigned addr = (unsigned)__cvta_generic_to_shared(&Bs_[brow * PADB + bcol]);
                ldsm4(bf[half * 2][0], bf[half * 2][1],
                      bf[half * 2 + 1][0], bf[half * 2 + 1][1], addr);
            }
#pragma unroll
            for (int mf = 0; mf < 4; mf++)
#pragma unroll
                for (int nf = 0; nf < 4; nf++)
                    mma_bf16(acc[mf][nf], a[mf], bf[nf]);
        }

        cur = (cur == 2) ? 0 : cur + 1;
        nxt = (nxt == 2) ? 0 : nxt + 1;
    }
#undef LOAD_STAGE

#pragma unroll
    for (int mf = 0; mf < 4; mf++)
#pragma unroll
        for (int nf = 0; nf < 4; nf++) {
            int r0 = row0 + wm + mf * 16 + (lane >> 2);
            int c0 = col0 + wn + nf * 8 + (lane & 3) * 2;
            *(float2*)&C[(size_t)r0 * NN + c0] =
                make_float2(acc[mf][nf][0], acc[mf][nf][1]);
            *(float2*)&C[(size_t)(r0 + 8) * NN + c0] =
                make_float2(acc[mf][nf][2], acc[mf][nf][3]);
        }
}

// ============================================================
// Kernel 2: softmax WITHOUT max pass (constant shift 48):
// read -> exp -> single sum reduction -> scale -> write.
// TWO rows per block, 256 threads, 2 float4/row/thread.
// ============================================================
__global__ __launch_bounds__(256) void softmax_kernel(float* __restrict__ scores)
{
    const int rowg0 = blockIdx.x * 2;
    const int i0 = rowg0 & (NN - 1);
    const int i1 = (rowg0 + 1) & (NN - 1);
    float* rowA = scores + (size_t)rowg0 * NN;
    float* rowB = rowA + NN;
    const int t = threadIdx.x;

    float4 a0 = ((float4*)rowA)[t];
    float4 a1 = ((float4*)rowA)[t + 256];
    float4 b0 = ((float4*)rowB)[t];
    float4 b1 = ((float4*)rowB)[t + 256];

    a0.x = __expf(a0.x - ESHIFT); a0.y = __expf(a0.y - ESHIFT);
    a0.z = __expf(a0.z - ESHIFT); a0.w = __expf(a0.w - ESHIFT);
    a1.x = __expf(a1.x - ESHIFT); a1.y = __expf(a1.y - ESHIFT);
    a1.z = __expf(a1.z - ESHIFT); a1.w = __expf(a1.w - ESHIFT);
    b0.x = __expf(b0.x - ESHIFT); b0.y = __expf(b0.y - ESHIFT);
    b0.z = __expf(b0.z - ESHIFT); b0.w = __expf(b0.w - ESHIFT);
    b1.x = __expf(b1.x - ESHIFT); b1.y = __expf(b1.y - ESHIFT);
    b1.z = __expf(b1.z - ESHIFT); b1.w = __expf(b1.w - ESHIFT);

    float sa = a0.x + a0.y + a0.z + a0.w + a1.x + a1.y + a1.z + a1.w;
    float sb = b0.x + b0.y + b0.z + b0.w + b1.x + b1.y + b1.z + b1.w;

    __shared__ float redA[8], redB[8];
#pragma unroll
    for (int o = 16; o > 0; o >>= 1) {
        sa += __shfl_xor_sync(0xffffffffu, sa, o);
        sb += __shfl_xor_sync(0xffffffffu, sb, o);
    }
    if ((t & 31) == 0) { redA[t >> 5] = sa; redB[t >> 5] = sb; }
    __syncthreads();
    float bsA = 0.0f, bsB = 0.0f;
#pragma unroll
    for (int w = 0; w < 8; w++) { bsA += redA[w]; bsB += redB[w]; }

    const float invA = 1.0f / bsA;
    const float invB = 1.0f / bsB;
    a0.x *= invA; a0.y *= invA; a0.z *= invA; a0.w *= invA;
    a1.x *= invA; a1.y *= invA; a1.z *= invA; a1.w *= invA;
    b0.x *= invB; b0.y *= invB; b0.z *= invB; b0.w *= invB;
    b1.x *= invB; b1.y *= invB; b1.z *= invB; b1.w *= invB;

    ((float4*)rowA)[t]       = a0;
    ((float4*)rowA)[t + 256] = a1;
    ((float4*)rowB)[t]       = b0;
    ((float4*)rowB)[t + 256] = b1;

    {
        int c0 = i0 >> 2, cc = i0 & 3;
        if (c0 == t) {
            float d = (cc == 0) ? a0.x : (cc == 1) ? a0.y : (cc == 2) ? a0.z : a0.w;
            g_diag[rowg0] = d;
        } else if (c0 == t + 256) {
            float d = (cc == 0) ? a1.x : (cc == 1) ? a1.y : (cc == 2) ? a1.z : a1.w;
            g_diag[rowg0] = d;
        }
    }
    {
        int c0 = i1 >> 2, cc = i1 & 3;
        if (c0 == t) {
            float d = (cc == 0) ? b0.x : (cc == 1) ? b0.y : (cc == 2) ? b0.z : b0.w;
            g_diag[rowg0 + 1] = d;
        } else if (c0 == t + 256) {
            float d = (cc == 0) ? b1.x : (cc == 1) ? b1.y : (cc == 2) ? b1.z : b1.w;
            g_diag[rowg0 + 1] = d;
        }
    }
}

// ============================================================
// Kernel 3a: rank counting — one WARP per element
// ============================================================
__global__ __launch_bounds__(256) void topk_count_kernel()
{
    const int b = blockIdx.y;
    __shared__ __align__(16) float v[NN];

    for (int i = threadIdx.x; i < NN / 4; i += 256)
        ((float4*)v)[i] = ((const float4*)(g_diag + b * NN))[i];
    __syncthreads();

    const int warp = threadIdx.x >> 5;
    const int lane = threadIdx.x & 31;
    const int i = blockIdx.x * 8 + warp;
    const float vi = v[i];

    int cnt = 0;
#pragma unroll 4
    for (int j4 = lane; j4 < NN / 4; j4 += 32) {
        float4 w = ((const float4*)v)[j4];
        int j = j4 * 4;
        cnt += (w.x > vi) || ((w.x == vi) && (j + 0 < i));
        cnt += (w.y > vi) || ((w.y == vi) && (j + 1 < i));
        cnt += (w.z > vi) || ((w.z == vi) && (j + 2 < i));
        cnt += (w.w > vi) || ((w.w == vi) && (j + 3 < i));
    }
#pragma unroll
    for (int o = 16; o > 0; o >>= 1) cnt += __shfl_xor_sync(0xffffffffu, cnt, o);

    if (lane == 0) g_sel[b * NN + i] = (cnt < KK) ? 1 : 0;
}

// ============================================================
// Kernel 3b: compaction via block scan
// ============================================================
__global__ __launch_bounds__(1024) void topk_compact_kernel()
{
    const int b = blockIdx.x;
    const int t = threadIdx.x;
    __shared__ int wsum[32];

    const int f0 = g_sel[b * NN + 2 * t];
    const int f1 = g_sel[b * NN + 2 * t + 1];
    const int mysum = f0 + f1;

    int inc = mysum;
#pragma unroll
    for (int o = 1; o < 32; o <<= 1) {
        int u = __shfl_up_sync(0xffffffffu, inc, o);
        if ((t & 31) >= o) inc += u;
    }
    if ((t & 31) == 31) wsum[t >> 5] = inc;
    __syncthreads();
    if (t < 32) {
        int wv = wsum[t];
#pragma unroll
        for (int o = 1; o < 32; o <<= 1) {
            int u = __shfl_up_sync(0xffffffffu, wv, o);
            if (t >= o) wv += u;
        }
        wsum[t] = wv;
    }
    __syncthreads();

    int excl = inc - mysum + ((t >> 5) ? wsum[(t >> 5) - 1] : 0);
    if (f0 && excl < KK)      g_topidx[b * KK + excl] = 2 * t;
    if (f1 && excl + f0 < KK) g_topidx[b * KK + excl + f0] = 2 * t + 1;
}

// ============================================================
// Kernel 4: rel top-R + soi triples; fully parallel scatter
// ============================================================
__global__ __launch_bounds__(128) void rel_kernel(
    const float* __restrict__ scores, float* __restrict__ soi_out)
{
    const int b  = blockIdx.y;
    const int tI = blockIdx.x;
    __shared__ float r[KK];
    __shared__ unsigned char sel[KK];

    const int ti = g_topidx[b * KK + tI];
    const int t  = threadIdx.x;

    if (t < KK) {
        int tj = g_topidx[b * KK + t];
        float val = scores[((size_t)b * NN + ti) * NN + tj];
        r[t] = (t == tI) ? BIGV : val;
    }
    __syncthreads();

    if (t < KK) {
        float vi = r[t];
        int cnt = 0;
#pragma unroll 4
        for (int j = 0; j < KK; j++) {
            float vj = r[j];
            cnt += (vj > vi) || ((vj == vi) && (j < t));
        }
        sel[t] = (cnt < RR) ? 1 : 0;
    }
    __syncthreads();

    if (t < KK && sel[t]) {
        int pos = 0;
#pragma unroll 4
        for (int j = 0; j < KK; j++) pos += (j < t) ? sel[j] : 0;
        if (pos < RR) {
            int obj = g_topidx[b * KK + t];
            int p = (b * KK + tI) * RR + pos;
            g_pairs[2 * p]     = ti;
            g_pairs[2 * p + 1] = obj;
            size_t so = (size_t)p * 3;
            soi_out[so + 0] = (float)b;
            soi_out[so + 1] = (float)ti;
            soi_out[so + 2] = (float)obj;
        }
    }
}

// ============================================================
// Kernel 5: re = LayerNorm(q[b,subj] + q[b,obj])
// ============================================================
__global__ __launch_bounds__(256) void re_kernel(
    const float* __restrict__ q, float* __restrict__ re_out)
{
    const int warp = threadIdx.x >> 5;
    const int lane = threadIdx.x & 31;
    const int p = blockIdx.x * 8 + warp;
    if (p >= BB * KK * RR) return;

    const int b = p / (KK * RR);
    const int subj = g_pairs[2 * p];
    const int obj  = g_pairs[2 * p + 1];
    const float4* qs = (const float4*)(q + ((size_t)b * NN + subj) * DD);
    const float4* qo = (const float4*)(q + ((size_t)b * NN + obj)  * DD);

    float x[8];
    float s = 0.0f, s2 = 0.0f;
#pragma unroll
    for (int c = 0; c < 2; c++) {
        float4 a = qs[lane + 32 * c];
        float4 o = qo[lane + 32 * c];
        x[4 * c + 0] = a.x + o.x; x[4 * c + 1] = a.y + o.y;
        x[4 * c + 2] = a.z + o.z; x[4 * c + 3] = a.w + o.w;
    }
#pragma unroll
    for (int e = 0; e < 8; e++) { s += x[e]; s2 += x[e] * x[e]; }
#pragma unroll
    for (int o = 16; o > 0; o >>= 1) {
        s  += __shfl_xor_sync(0xffffffffu, s,  o);
        s2 += __shfl_xor_sync(0xffffffffu, s2, o);
    }
    const float mu  = s * (1.0f / DD);
    const float var = s2 * (1.0f / DD) - mu * mu;
    const float inv = rsqrtf(var + LN_EPS);

    float4* dst = (float4*)(re_out + (size_t)p * DD);
#pragma unroll
    for (int c = 0; c < 2; c++) {
        float4 r;
        r.x = (x[4 * c + 0] - mu) * inv;
        r.y = (x[4 * c + 1] - mu) * inv;
        r.z = (x[4 * c + 2] - mu) * inv;
        r.w = (x[4 * c + 3] - mu) * inv;
        dst[lane + 32 * c] = r;
    }
}

// ============================================================
extern "C" void kernel_launch(void* const* d_in, const int* in_sizes, int n_in,
                              void* d_out, int out_size)
{
    const float* q = (const float*)d_in[0];
    const float* k = (const float*)d_in[1];

    float* scores = (float*)d_out;
    float* soi    = scores + (size_t)BB * NN * NN;
    float* re     = soi + (size_t)BB * KK * RR * 3;

    void *qs_ptr = nullptr, *ks_ptr = nullptr;
    cudaGetSymbolAddress(&qs_ptr, g_qsb);
    cudaGetSymbolAddress(&ks_ptr, g_ksb);

    cudaFuncSetAttribute(gemm_bf16k, cudaFuncAttributeMaxDynamicSharedMemorySize, SMEM_BYTES);

    split3b_kernel<<<dim3(BB * NN * DD / 8 / 256, 2), 256>>>(q, k);
    gemm_bf16k<<<dim3(NN / BN, NN / BM, BB), 256, SMEM_BYTES>>>(
        (const __nv_bfloat16*)qs_ptr, (const __nv_bfloat16*)ks_ptr, scores);
    softmax_kernel<<<BB * NN / 2, 256>>>(scores);
    topk_count_kernel<<<dim3(NN / 8, BB), 256>>>();
    topk_compact_kernel<<<BB, 1024>>>();
    rel_kernel<<<dim3(KK, BB), 128>>>(scores, soi);
    re_kernel<<<(BB * KK * RR + 7) / 8, 256>>>(q, re);
}

// round 14
// speedup vs baseline: 1.0768x; 1.0407x over previous
#include <cuda_runtime.h>
#include <cuda_bf16.h>
#include <cstdint>

#define BB 8
#define NN 2048
#define DD 256
#define K3 768            // 3-term split K' = 3*DD (bf16)
#define KK 100
#define RR 5
#define BIGV 1000000000.0f
#define LN_EPS 1e-5f
#define ESHIFT 48.0f

// GEMM tiling
#define BM 128
#define BN 128
#define BKE 64                         // bf16 elems per stage (128 B/row)
#define PADB 72                        // padded row stride in bf16 elems
#define STAGE_H (2 * BM * PADB)        // halves per stage (A+B) = 18432
#define NSTG 3
#define SMEM_BYTES (NSTG * STAGE_H * 2)   // 110592

// ---- scratch (device globals; no allocations allowed) ----
__device__ __align__(128) __nv_bfloat16 g_qsb[(size_t)BB * NN * K3];
__device__ __align__(128) __nv_bfloat16 g_ksb[(size_t)BB * NN * K3];
__device__ float g_diag[BB * NN];
__device__ int   g_sel[BB * NN];
__device__ int   g_topidx[BB * KK];
__device__ int   g_pairs[BB * KK * RR * 2];

// ============================================================
// helpers
// ============================================================
__device__ __forceinline__ void ldsm4(unsigned& r0, unsigned& r1, unsigned& r2, unsigned& r3,
                                      unsigned addr) {
    asm volatile("ldmatrix.sync.aligned.m8n8.x4.shared.b16 {%0,%1,%2,%3}, [%4];"
                 : "=r"(r0), "=r"(r1), "=r"(r2), "=r"(r3) : "r"(addr));
}
__device__ __forceinline__ void mma_bf16(float* d, const unsigned* a, const unsigned* b) {
    asm volatile("mma.sync.aligned.m16n8k16.row.col.f32.bf16.bf16.f32 "
                 "{%0,%1,%2,%3},{%4,%5,%6,%7},{%8,%9},{%0,%1,%2,%3};"
                 : "+f"(d[0]), "+f"(d[1]), "+f"(d[2]), "+f"(d[3])
                 : "r"(a[0]), "r"(a[1]), "r"(a[2]), "r"(a[3]), "r"(b[0]), "r"(b[1]));
}
__device__ __forceinline__ void cpa16(void* smem_dst, const void* gsrc) {
    unsigned d = (unsigned)__cvta_generic_to_shared(smem_dst);
    asm volatile("cp.async.cg.shared.global [%0], [%1], 16;" :: "r"(d), "l"(gsrc));
}

// ============================================================
// Kernel 0: bf16 3-term split.  q -> [qh,qh,ql] ; k -> [kh,kl,kh]
// ============================================================
__global__ __launch_bounds__(256) void split3b_kernel(
    const float* __restrict__ q, const float* __restrict__ k)
{
    const bool isK = blockIdx.y != 0;
    const float4* src = (const float4*)(isK ? k : q);
    __nv_bfloat16* dst = isK ? g_ksb : g_qsb;
    size_t i = (size_t)blockIdx.x * 256 + threadIdx.x;

    float4 v0 = src[2 * i];
    float4 v1 = src[2 * i + 1];
    float xs[8] = {v0.x, v0.y, v0.z, v0.w, v1.x, v1.y, v1.z, v1.w};

    __align__(16) __nv_bfloat16 out[24];
#pragma unroll
    for (int e = 0; e < 8; e++) {
        __nv_bfloat16 h = __float2bfloat16(xs[e]);
        __nv_bfloat16 l = __float2bfloat16(xs[e] - __bfloat162float(h));
        if (!isK) { out[3 * e] = h; out[3 * e + 1] = h; out[3 * e + 2] = l; }
        else      { out[3 * e] = h; out[3 * e + 1] = l; out[3 * e + 2] = h; }
    }
    uint4* o = (uint4*)(dst + 24 * i);
    o[0] = ((uint4*)out)[0];
    o[1] = ((uint4*)out)[1];
    o[2] = ((uint4*)out)[2];
}

// ============================================================
// Kernel 1: bf16 mma.sync m16n8k16 GEMM over K'=768
// 3-stage cp.async pipeline, ONE __syncthreads per iteration
// ============================================================
__global__ __launch_bounds__(256, 2) void gemm_bf16k(
    const __nv_bfloat16* __restrict__ A0, const __nv_bfloat16* __restrict__ B0,
    float* __restrict__ out)
{
    extern __shared__ __nv_bfloat16 sm[];
    const int b = blockIdx.z;
    const int row0 = blockIdx.y * BM;
    const int col0 = blockIdx.x * BN;
    const __nv_bfloat16* A  = A0 + (size_t)b * NN * K3;
    const __nv_bfloat16* Bm = B0 + (size_t)b * NN * K3;
    float* C = out + (size_t)b * NN * NN;

    const int tid = threadIdx.x;
    const int warp = tid >> 5, lane = tid & 31;
    const int wm = (warp >> 2) * 64;
    const int wn = (warp & 3) * 32;

    float acc[4][4][4];
#pragma unroll
    for (int mf = 0; mf < 4; mf++)
#pragma unroll
        for (int nf = 0; nf < 4; nf++)
#pragma unroll
            for (int e = 0; e < 4; e++) acc[mf][nf][e] = 0.0f;

#define LOAD_STAGE(s, kt)                                                      \
    do {                                                                       \
        __nv_bfloat16* As_ = sm + (s) * STAGE_H;                               \
        __nv_bfloat16* Bs_ = As_ + BM * PADB;                                  \
        _Pragma("unroll")                                                      \
        for (int l = 0; l < 4; l++) {                                          \
            int idx = tid + l * 256;                                           \
            int row = idx >> 3;                                                \
            int ce  = (idx & 7) * 8;                                           \
            cpa16(&As_[row * PADB + ce], &A [(size_t)(row0 + row) * K3 + (kt) + ce]); \
            cpa16(&Bs_[row * PADB + ce], &Bm[(size_t)(col0 + row) * K3 + (kt) + ce]); \
        }                                                                      \
        asm volatile("cp.async.commit_group;");                                \
    } while (0)

    LOAD_STAGE(0, 0);
    LOAD_STAGE(1, BKE);

    const int NT = K3 / BKE;   // 12
    int cur = 0, nxt = 2;
    for (int t = 0; t < NT; t++) {
        if (t < NT - 1) { asm volatile("cp.async.wait_group 1;"); }
        else            { asm volatile("cp.async.wait_group 0;"); }
        __syncthreads();

        if (t + 2 < NT) {
            LOAD_STAGE(nxt, (t + 2) * BKE);
        }

        const __nv_bfloat16* As_ = sm + cur * STAGE_H;
        const __nv_bfloat16* Bs_ = As_ + BM * PADB;

#pragma unroll
        for (int kk = 0; kk < 4; kk++) {
            const int kb = kk * 16;

            unsigned a[4][4];
#pragma unroll
            for (int mf = 0; mf < 4; mf++) {
                int arow = wm + mf * 16 + (lane & 15);
                int acol = kb + ((lane >> 4) << 3);
                unsigned addr = (unsigned)__cvta_generic_to_shared(&As_[arow * PADB + acol]);
                ldsm4(a[mf][0], a[mf][1], a[mf][2], a[mf][3], addr);
            }
            unsigned bf[4][2];
#pragma unroll
            for (int half = 0; half < 2; half++) {
                int brow = wn + half * 16 + (lane & 7) + ((lane >> 4) << 3);
                int bcol = kb + (((lane >> 3) & 1) << 3);
                unsigned addr = (unsigned)__cvta_generic_to_shared(&Bs_[brow * PADB + bcol]);
                ldsm4(bf[half * 2][0], bf[half * 2][1],
                      bf[half * 2 + 1][0], bf[half * 2 + 1][1], addr);
            }
#pragma unroll
            for (int mf = 0; mf < 4; mf++)
#pragma unroll
                for (int nf = 0; nf < 4; nf++)
                    mma_bf16(acc[mf][nf], a[mf], bf[nf]);
        }

        cur = (cur == 2) ? 0 : cur + 1;
        nxt = (nxt == 2) ? 0 : nxt + 1;
    }
#undef LOAD_STAGE

#pragma unroll
    for (int mf = 0; mf < 4; mf++)
#pragma unroll
        for (int nf = 0; nf < 4; nf++) {
            int r0 = row0 + wm + mf * 16 + (lane >> 2);
            int c0 = col0 + wn + nf * 8 + (lane & 3) * 2;
            *(float2*)&C[(size_t)r0 * NN + c0] =
                make_float2(acc[mf][nf][0], acc[mf][nf][1]);
            *(float2*)&C[(size_t)(r0 + 8) * NN + c0] =
                make_float2(acc[mf][nf][2], acc[mf][nf][3]);
        }
}

// ============================================================
// Kernel 2: softmax without max pass (constant shift 48).
// TWO rows per block; blocks mapped to rows in REVERSE order so
// the first-scheduled blocks read the GEMM's last-written
// (still L2-resident) scores.
// ============================================================
__global__ __launch_bounds__(256) void softmax_kernel(float* __restrict__ scores)
{
    const int rowg0 = (gridDim.x - 1 - blockIdx.x) * 2;   // reversed mapping
    const int i0 = rowg0 & (NN - 1);
    const int i1 = (rowg0 + 1) & (NN - 1);
    float* rowA = scores + (size_t)rowg0 * NN;
    float* rowB = rowA + NN;
    const int t = threadIdx.x;

    float4 a0 = ((float4*)rowA)[t];
    float4 a1 = ((float4*)rowA)[t + 256];
    float4 b0 = ((float4*)rowB)[t];
    float4 b1 = ((float4*)rowB)[t + 256];

    a0.x = __expf(a0.x - ESHIFT); a0.y = __expf(a0.y - ESHIFT);
    a0.z = __expf(a0.z - ESHIFT); a0.w = __expf(a0.w - ESHIFT);
    a1.x = __expf(a1.x - ESHIFT); a1.y = __expf(a1.y - ESHIFT);
    a1.z = __expf(a1.z - ESHIFT); a1.w = __expf(a1.w - ESHIFT);
    b0.x = __expf(b0.x - ESHIFT); b0.y = __expf(b0.y - ESHIFT);
    b0.z = __expf(b0.z - ESHIFT); b0.w = __expf(b0.w - ESHIFT);
    b1.x = __expf(b1.x - ESHIFT); b1.y = __expf(b1.y - ESHIFT);
    b1.z = __expf(b1.z - ESHIFT); b1.w = __expf(b1.w - ESHIFT);

    float sa = a0.x + a0.y + a0.z + a0.w + a1.x + a1.y + a1.z + a1.w;
    float sb = b0.x + b0.y + b0.z + b0.w + b1.x + b1.y + b1.z + b1.w;

    __shared__ float redA[8], redB[8];
#pragma unroll
    for (int o = 16; o > 0; o >>= 1) {
        sa += __shfl_xor_sync(0xffffffffu, sa, o);
        sb += __shfl_xor_sync(0xffffffffu, sb, o);
    }
    if ((t & 31) == 0) { redA[t >> 5] = sa; redB[t >> 5] = sb; }
    __syncthreads();
    float bsA = 0.0f, bsB = 0.0f;
#pragma unroll
    for (int w = 0; w < 8; w++) { bsA += redA[w]; bsB += redB[w]; }

    const float invA = 1.0f / bsA;
    const float invB = 1.0f / bsB;
    a0.x *= invA; a0.y *= invA; a0.z *= invA; a0.w *= invA;
    a1.x *= invA; a1.y *= invA; a1.z *= invA; a1.w *= invA;
    b0.x *= invB; b0.y *= invB; b0.z *= invB; b0.w *= invB;
    b1.x *= invB; b1.y *= invB; b1.z *= invB; b1.w *= invB;

    ((float4*)rowA)[t]       = a0;
    ((float4*)rowA)[t + 256] = a1;
    ((float4*)rowB)[t]       = b0;
    ((float4*)rowB)[t + 256] = b1;

    {
        int c0 = i0 >> 2, cc = i0 & 3;
        if (c0 == t) {
            float d = (cc == 0) ? a0.x : (cc == 1) ? a0.y : (cc == 2) ? a0.z : a0.w;
            g_diag[rowg0] = d;
        } else if (c0 == t + 256) {
            float d = (cc == 0) ? a1.x : (cc == 1) ? a1.y : (cc == 2) ? a1.z : a1.w;
            g_diag[rowg0] = d;
        }
    }
    {
        int c0 = i1 >> 2, cc = i1 & 3;
        if (c0 == t) {
            float d = (cc == 0) ? b0.x : (cc == 1) ? b0.y : (cc == 2) ? b0.z : b0.w;
            g_diag[rowg0 + 1] = d;
        } else if (c0 == t + 256) {
            float d = (cc == 0) ? b1.x : (cc == 1) ? b1.y : (cc == 2) ? b1.z : b1.w;
            g_diag[rowg0 + 1] = d;
        }
    }
}

// ============================================================
// Kernel 3a: rank counting — one WARP per element.
// Two-regime compare (i warp-uniform): j<i uses >=, j>i uses >,
// single straddling float4 uses the exact tie-break expression.
// ============================================================
__global__ __launch_bounds__(256) void topk_count_kernel()
{
    const int b = blockIdx.y;
    __shared__ __align__(16) float v[NN];

    for (int i = threadIdx.x; i < NN / 4; i += 256)
        ((float4*)v)[i] = ((const float4*)(g_diag + b * NN))[i];
    __syncthreads();

    const int warp = threadIdx.x >> 5;
    const int lane = threadIdx.x & 31;
    const int i = blockIdx.x * 8 + warp;
    const float vi = v[i];
    const int i4 = i >> 2;

    int cnt = 0;
#pragma unroll 4
    for (int j4 = lane; j4 < NN / 4; j4 += 32) {
        float4 w = ((const float4*)v)[j4];
        if (j4 < i4) {
            cnt += (w.x >= vi);
            cnt += (w.y >= vi);
            cnt += (w.z >= vi);
            cnt += (w.w >= vi);
        } else if (j4 > i4) {
            cnt += (w.x > vi);
            cnt += (w.y > vi);
            cnt += (w.z > vi);
            cnt += (w.w > vi);
        } else {
            int j = j4 * 4;
            cnt += (w.x > vi) || ((w.x == vi) && (j + 0 < i));
            cnt += (w.y > vi) || ((w.y == vi) && (j + 1 < i));
            cnt += (w.z > vi) || ((w.z == vi) && (j + 2 < i));
            cnt += (w.w > vi) || ((w.w == vi) && (j + 3 < i));
        }
    }
#pragma unroll
    for (int o = 16; o > 0; o >>= 1) cnt += __shfl_xor_sync(0xffffffffu, cnt, o);

    if (lane == 0) g_sel[b * NN + i] = (cnt < KK) ? 1 : 0;
}

// ============================================================
// Kernel 3b: compaction via block scan
// ============================================================
__global__ __launch_bounds__(1024) void topk_compact_kernel()
{
    const int b = blockIdx.x;
    const int t = threadIdx.x;
    __shared__ int wsum[32];

    const int f0 = g_sel[b * NN + 2 * t];
    const int f1 = g_sel[b * NN + 2 * t + 1];
    const int mysum = f0 + f1;

    int inc = mysum;
#pragma unroll
    for (int o = 1; o < 32; o <<= 1) {
        int u = __shfl_up_sync(0xffffffffu, inc, o);
        if ((t & 31) >= o) inc += u;
    }
    if ((t & 31) == 31) wsum[t >> 5] = inc;
    __syncthreads();
    if (t < 32) {
        int wv = wsum[t];
#pragma unroll
        for (int o = 1; o < 32; o <<= 1) {
            int u = __shfl_up_sync(0xffffffffu, wv, o);
            if (t >= o) wv += u;
        }
        wsum[t] = wv;
    }
    __syncthreads();

    int excl = inc - mysum + ((t >> 5) ? wsum[(t >> 5) - 1] : 0);
    if (f0 && excl < KK)      g_topidx[b * KK + excl] = 2 * t;
    if (f1 && excl + f0 < KK) g_topidx[b * KK + excl + f0] = 2 * t + 1;
}

// ============================================================
// Kernel 4: rel top-R + soi triples; fully parallel scatter
// ============================================================
__global__ __launch_bounds__(128) void rel_kernel(
    const float* __restrict__ scores, float* __restrict__ soi_out)
{
    const int b  = blockIdx.y;
    const int tI = blockIdx.x;
    __shared__ float r[KK];
    __shared__ unsigned char sel[KK];

    const int ti = g_topidx[b * KK + tI];
    const int t  = threadIdx.x;

    if (t < KK) {
        int tj = g_topidx[b * KK + t];
        float val = scores[((size_t)b * NN + ti) * NN + tj];
        r[t] = (t == tI) ? BIGV : val;
    }
    __syncthreads();

    if (t < KK) {
        float vi = r[t];
        int cnt = 0;
#pragma unroll 4
        for (int j = 0; j < KK; j++) {
            float vj = r[j];
            cnt += (vj > vi) || ((vj == vi) && (j < t));
        }
        sel[t] = (cnt < RR) ? 1 : 0;
    }
    __syncthreads();

    if (t < KK && sel[t]) {
        int pos = 0;
#pragma unroll 4
        for (int j = 0; j < KK; j++) pos += (j < t) ? sel[j] : 0;
        if (pos < RR) {
            int obj = g_topidx[b * KK + t];
            int p = (b * KK + tI) * RR + pos;
            g_pairs[2 * p]     = ti;
            g_pairs[2 * p + 1] = obj;
            size_t so = (size_t)p * 3;
            soi_out[so + 0] = (float)b;
            soi_out[so + 1] = (float)ti;
            soi_out[so + 2] = (float)obj;
        }
    }
}

// ============================================================
// Kernel 5: re = LayerNorm(q[b,subj] + q[b,obj])
// ============================================================
__global__ __launch_bounds__(256) void re_kernel(
    const float* __restrict__ q, float* __restrict__ re_out)
{
    const int warp = threadIdx.x >> 5;
    const int lane = threadIdx.x & 31;
    const int p = blockIdx.x * 8 + warp;
    if (p >= BB * KK * RR) return;

    const int b = p / (KK * RR);
    const int subj = g_pairs[2 * p];
    const int obj  = g_pairs[2 * p + 1];
    const float4* qs = (const float4*)(q + ((size_t)b * NN + subj) * DD);
    const float4* qo = (const float4*)(q + ((size_t)b * NN + obj)  * DD);

    float x[8];
    float s = 0.0f, s2 = 0.0f;
#pragma unroll
    for (int c = 0; c < 2; c++) {
        float4 a = qs[lane + 32 * c];
        float4 o = qo[lane + 32 * c];
        x[4 * c + 0] = a.x + o.x; x[4 * c + 1] = a.y + o.y;
        x[4 * c + 2] = a.z + o.z; x[4 * c + 3] = a.w + o.w;
    }
#pragma unroll
    for (int e = 0; e < 8; e++) { s += x[e]; s2 += x[e] * x[e]; }
#pragma unroll
    for (int o = 16; o > 0; o >>= 1) {
        s  += __shfl_xor_sync(0xffffffffu, s,  o);
        s2 += __shfl_xor_sync(0xffffffffu, s2, o);
    }
    const float mu  = s * (1.0f / DD);
    const float var = s2 * (1.0f / DD) - mu * mu;
    const float inv = rsqrtf(var + LN_EPS);

    float4* dst = (float4*)(re_out + (size_t)p * DD);
#pragma unroll
    for (int c = 0; c < 2; c++) {
        float4 r;
        r.x = (x[4 * c + 0] - mu) * inv;
        r.y = (x[4 * c + 1] - mu) * inv;
        r.z = (x[4 * c + 2] - mu) * inv;
        r.w = (x[4 * c + 3] - mu) * inv;
        dst[lane + 32 * c] = r;
    }
}

// ============================================================
extern "C" void kernel_launch(void* const* d_in, const int* in_sizes, int n_in,
                              void* d_out, int out_size)
{
    const float* q = (const float*)d_in[0];
    const float* k = (const float*)d_in[1];

    float* scores = (float*)d_out;
    float* soi    = scores + (size_t)BB * NN * NN;
    float* re     = soi + (size_t)BB * KK * RR * 3;

    void *qs_ptr = nullptr, *ks_ptr = nullptr;
    cudaGetSymbolAddress(&qs_ptr, g_qsb);
    cudaGetSymbolAddress(&ks_ptr, g_ksb);

    cudaFuncSetAttribute(gemm_bf16k, cudaFuncAttributeMaxDynamicSharedMemorySize, SMEM_BYTES);

    split3b_kernel<<<dim3(BB * NN * DD / 8 / 256, 2), 256>>>(q, k);
    gemm_bf16k<<<dim3(NN / BN, NN / BM, BB), 256, SMEM_BYTES>>>(
        (const __nv_bfloat16*)qs_ptr, (const __nv_bfloat16*)ks_ptr, scores);
    softmax_kernel<<<BB * NN / 2, 256>>>(scores);
    topk_count_kernel<<<dim3(NN / 8, BB), 256>>>();
    topk_compact_kernel<<<BB, 1024>>>();
    rel_kernel<<<dim3(KK, BB), 128>>>(scores, soi);
    re_kernel<<<(BB * KK * RR + 7) / 8, 256>>>(q, re);
}

// round 15
// speedup vs baseline: 1.0833x; 1.0060x over previous
#include <cuda_runtime.h>
#include <cuda_bf16.h>
#include <cstdint>

#define BB 8
#define NN 2048
#define DD 256
#define K3 768            // 3-term split K' = 3*DD (bf16)
#define KK 100
#define RR 5
#define BIGV 1000000000.0f
#define LN_EPS 1e-5f
#define ESHIFT 48.0f

// GEMM tiling
#define BM 128
#define BN 128
#define BKE 64                         // bf16 elems per stage (128 B/row)
#define PADB 72                        // padded row stride in bf16 elems
#define STAGE_H (2 * BM * PADB)        // halves per stage (A+B) = 18432
#define NSTG 3
#define SMEM_BYTES (NSTG * STAGE_H * 2)   // 110592

// ---- scratch (device globals; no allocations allowed) ----
__device__ __align__(128) __nv_bfloat16 g_qsb[(size_t)BB * NN * K3];
__device__ __align__(128) __nv_bfloat16 g_ksb[(size_t)BB * NN * K3];
__device__ float g_diag[BB * NN];
__device__ int   g_sel[BB * NN];
__device__ int   g_topidx[BB * KK];
__device__ int   g_pairs[BB * KK * RR * 2];

// ============================================================
// helpers
// ============================================================
__device__ __forceinline__ void ldsm4(unsigned& r0, unsigned& r1, unsigned& r2, unsigned& r3,
                                      unsigned addr) {
    asm volatile("ldmatrix.sync.aligned.m8n8.x4.shared.b16 {%0,%1,%2,%3}, [%4];"
                 : "=r"(r0), "=r"(r1), "=r"(r2), "=r"(r3) : "r"(addr));
}
__device__ __forceinline__ void mma_bf16(float* d, const unsigned* a, const unsigned* b) {
    asm volatile("mma.sync.aligned.m16n8k16.row.col.f32.bf16.bf16.f32 "
                 "{%0,%1,%2,%3},{%4,%5,%6,%7},{%8,%9},{%0,%1,%2,%3};"
                 : "+f"(d[0]), "+f"(d[1]), "+f"(d[2]), "+f"(d[3])
                 : "r"(a[0]), "r"(a[1]), "r"(a[2]), "r"(a[3]), "r"(b[0]), "r"(b[1]));
}
__device__ __forceinline__ void cpa16(void* smem_dst, const void* gsrc) {
    unsigned d = (unsigned)__cvta_generic_to_shared(smem_dst);
    asm volatile("cp.async.cg.shared.global [%0], [%1], 16;" :: "r"(d), "l"(gsrc));
}

// ============================================================
// Kernel 0: bf16 3-term split.  q -> [qh,qh,ql] ; k -> [kh,kl,kh]
// ============================================================
__global__ __launch_bounds__(256) void split3b_kernel(
    const float* __restrict__ q, const float* __restrict__ k)
{
    const bool isK = blockIdx.y != 0;
    const float4* src = (const float4*)(isK ? k : q);
    __nv_bfloat16* dst = isK ? g_ksb : g_qsb;
    size_t i = (size_t)blockIdx.x * 256 + threadIdx.x;

    float4 v0 = src[2 * i];
    float4 v1 = src[2 * i + 1];
    float xs[8] = {v0.x, v0.y, v0.z, v0.w, v1.x, v1.y, v1.z, v1.w};

    __align__(16) __nv_bfloat16 out[24];
#pragma unroll
    for (int e = 0; e < 8; e++) {
        __nv_bfloat16 h = __float2bfloat16(xs[e]);
        __nv_bfloat16 l = __float2bfloat16(xs[e] - __bfloat162float(h));
        if (!isK) { out[3 * e] = h; out[3 * e + 1] = h; out[3 * e + 2] = l; }
        else      { out[3 * e] = h; out[3 * e + 1] = l; out[3 * e + 2] = h; }
    }
    uint4* o = (uint4*)(dst + 24 * i);
    o[0] = ((uint4*)out)[0];
    o[1] = ((uint4*)out)[1];
    o[2] = ((uint4*)out)[2];
}

// ============================================================
// Kernel 1: bf16 mma.sync m16n8k16 GEMM over K'=768
// 3-stage cp.async pipeline, ONE __syncthreads per iteration
// ============================================================
__global__ __launch_bounds__(256, 2) void gemm_bf16k(
    const __nv_bfloat16* __restrict__ A0, const __nv_bfloat16* __restrict__ B0,
    float* __restrict__ out)
{
    extern __shared__ __nv_bfloat16 sm[];
    const int b = blockIdx.z;
    const int row0 = blockIdx.y * BM;
    const int col0 = blockIdx.x * BN;
    const __nv_bfloat16* A  = A0 + (size_t)b * NN * K3;
    const __nv_bfloat16* Bm = B0 + (size_t)b * NN * K3;
    float* C = out + (size_t)b * NN * NN;

    const int tid = threadIdx.x;
    const int warp = tid >> 5, lane = tid & 31;
    const int wm = (warp >> 2) * 64;
    const int wn = (warp & 3) * 32;

    float acc[4][4][4];
#pragma unroll
    for (int mf = 0; mf < 4; mf++)
#pragma unroll
        for (int nf = 0; nf < 4; nf++)
#pragma unroll
            for (int e = 0; e < 4; e++) acc[mf][nf][e] = 0.0f;

#define LOAD_STAGE(s, kt)                                                      \
    do {                                                                       \
        __nv_bfloat16* As_ = sm + (s) * STAGE_H;                               \
        __nv_bfloat16* Bs_ = As_ + BM * PADB;                                  \
        _Pragma("unroll")                                                      \
        for (int l = 0; l < 4; l++) {                                          \
            int idx = tid + l * 256;                                           \
            int row = idx >> 3;                                                \
            int ce  = (idx & 7) * 8;                                           \
            cpa16(&As_[row * PADB + ce], &A [(size_t)(row0 + row) * K3 + (kt) + ce]); \
            cpa16(&Bs_[row * PADB + ce], &Bm[(size_t)(col0 + row) * K3 + (kt) + ce]); \
        }                                                                      \
        asm volatile("cp.async.commit_group;");                                \
    } while (0)

    LOAD_STAGE(0, 0);
    LOAD_STAGE(1, BKE);

    const int NT = K3 / BKE;   // 12
    int cur = 0, nxt = 2;
    for (int t = 0; t < NT; t++) {
        if (t < NT - 1) { asm volatile("cp.async.wait_group 1;"); }
        else            { asm volatile("cp.async.wait_group 0;"); }
        __syncthreads();

        if (t + 2 < NT) {
            LOAD_STAGE(nxt, (t + 2) * BKE);
        }

        const __nv_bfloat16* As_ = sm + cur * STAGE_H;
        const __nv_bfloat16* Bs_ = As_ + BM * PADB;

#pragma unroll
        for (int kk = 0; kk < 4; kk++) {
            const int kb = kk * 16;

            unsigned a[4][4];
#pragma unroll
            for (int mf = 0; mf < 4; mf++) {
                int arow = wm + mf * 16 + (lane & 15);
                int acol = kb + ((lane >> 4) << 3);
                unsigned addr = (unsigned)__cvta_generic_to_shared(&As_[arow * PADB + acol]);
                ldsm4(a[mf][0], a[mf][1], a[mf][2], a[mf][3], addr);
            }
            unsigned bf[4][2];
#pragma unroll
            for (int half = 0; half < 2; half++) {
                int brow = wn + half * 16 + (lane & 7) + ((lane >> 4) << 3);
                int bcol = kb + (((lane >> 3) & 1) << 3);
                unsigned addr = (unsigned)__cvta_generic_to_shared(&Bs_[brow * PADB + bcol]);
                ldsm4(bf[half * 2][0], bf[half * 2][1],
                      bf[half * 2 + 1][0], bf[half * 2 + 1][1], addr);
            }
#pragma unroll
            for (int mf = 0; mf < 4; mf++)
#pragma unroll
                for (int nf = 0; nf < 4; nf++)
                    mma_bf16(acc[mf][nf], a[mf], bf[nf]);
        }

        cur = (cur == 2) ? 0 : cur + 1;
        nxt = (nxt == 2) ? 0 : nxt + 1;
    }
#undef LOAD_STAGE

#pragma unroll
    for (int mf = 0; mf < 4; mf++)
#pragma unroll
        for (int nf = 0; nf < 4; nf++) {
            int r0 = row0 + wm + mf * 16 + (lane >> 2);
            int c0 = col0 + wn + nf * 8 + (lane & 3) * 2;
            *(float2*)&C[(size_t)r0 * NN + c0] =
                make_float2(acc[mf][nf][0], acc[mf][nf][1]);
            *(float2*)&C[(size_t)(r0 + 8) * NN + c0] =
                make_float2(acc[mf][nf][2], acc[mf][nf][3]);
        }
}

// ============================================================
// Kernel 2: softmax without max pass (constant shift 48).
// TWO rows per block; reversed block->row mapping (L2 tail chase)
// ============================================================
__global__ __launch_bounds__(256) void softmax_kernel(float* __restrict__ scores)
{
    const int rowg0 = (gridDim.x - 1 - blockIdx.x) * 2;   // reversed mapping
    const int i0 = rowg0 & (NN - 1);
    const int i1 = (rowg0 + 1) & (NN - 1);
    float* rowA = scores + (size_t)rowg0 * NN;
    float* rowB = rowA + NN;
    const int t = threadIdx.x;

    float4 a0 = ((float4*)rowA)[t];
    float4 a1 = ((float4*)rowA)[t + 256];
    float4 b0 = ((float4*)rowB)[t];
    float4 b1 = ((float4*)rowB)[t + 256];

    a0.x = __expf(a0.x - ESHIFT); a0.y = __expf(a0.y - ESHIFT);
    a0.z = __expf(a0.z - ESHIFT); a0.w = __expf(a0.w - ESHIFT);
    a1.x = __expf(a1.x - ESHIFT); a1.y = __expf(a1.y - ESHIFT);
    a1.z = __expf(a1.z - ESHIFT); a1.w = __expf(a1.w - ESHIFT);
    b0.x = __expf(b0.x - ESHIFT); b0.y = __expf(b0.y - ESHIFT);
    b0.z = __expf(b0.z - ESHIFT); b0.w = __expf(b0.w - ESHIFT);
    b1.x = __expf(b1.x - ESHIFT); b1.y = __expf(b1.y - ESHIFT);
    b1.z = __expf(b1.z - ESHIFT); b1.w = __expf(b1.w - ESHIFT);

    float sa = a0.x + a0.y + a0.z + a0.w + a1.x + a1.y + a1.z + a1.w;
    float sb = b0.x + b0.y + b0.z + b0.w + b1.x + b1.y + b1.z + b1.w;

    __shared__ float redA[8], redB[8];
#pragma unroll
    for (int o = 16; o > 0; o >>= 1) {
        sa += __shfl_xor_sync(0xffffffffu, sa, o);
        sb += __shfl_xor_sync(0xffffffffu, sb, o);
    }
    if ((t & 31) == 0) { redA[t >> 5] = sa; redB[t >> 5] = sb; }
    __syncthreads();
    float bsA = 0.0f, bsB = 0.0f;
#pragma unroll
    for (int w = 0; w < 8; w++) { bsA += redA[w]; bsB += redB[w]; }

    const float invA = 1.0f / bsA;
    const float invB = 1.0f / bsB;
    a0.x *= invA; a0.y *= invA; a0.z *= invA; a0.w *= invA;
    a1.x *= invA; a1.y *= invA; a1.z *= invA; a1.w *= invA;
    b0.x *= invB; b0.y *= invB; b0.z *= invB; b0.w *= invB;
    b1.x *= invB; b1.y *= invB; b1.z *= invB; b1.w *= invB;

    ((float4*)rowA)[t]       = a0;
    ((float4*)rowA)[t + 256] = a1;
    ((float4*)rowB)[t]       = b0;
    ((float4*)rowB)[t + 256] = b1;

    {
        int c0 = i0 >> 2, cc = i0 & 3;
        if (c0 == t) {
            float d = (cc == 0) ? a0.x : (cc == 1) ? a0.y : (cc == 2) ? a0.z : a0.w;
            g_diag[rowg0] = d;
        } else if (c0 == t + 256) {
            float d = (cc == 0) ? a1.x : (cc == 1) ? a1.y : (cc == 2) ? a1.z : a1.w;
            g_diag[rowg0] = d;
        }
    }
    {
        int c0 = i1 >> 2, cc = i1 & 3;
        if (c0 == t) {
            float d = (cc == 0) ? b0.x : (cc == 1) ? b0.y : (cc == 2) ? b0.z : b0.w;
            g_diag[rowg0 + 1] = d;
        } else if (c0 == t + 256) {
            float d = (cc == 0) ? b1.x : (cc == 1) ? b1.y : (cc == 2) ? b1.z : b1.w;
            g_diag[rowg0 + 1] = d;
        }
    }
}

// ============================================================
// Kernel 3a: rank counting — one warp per FOUR consecutive
// elements (i_base 4-aligned: all 4 share the straddling float4).
// grid (NN/32, BB), block 256 (8 warps x 4 elems = 32/block).
// ============================================================
__global__ __launch_bounds__(256) void topk_count_kernel()
{
    const int b = blockIdx.y;
    __shared__ __align__(16) float v[NN];

    for (int i = threadIdx.x; i < NN / 4; i += 256)
        ((float4*)v)[i] = ((const float4*)(g_diag + b * NN))[i];
    __syncthreads();

    const int warp = threadIdx.x >> 5;
    const int lane = threadIdx.x & 31;
    const int ib = blockIdx.x * 32 + warp * 4;   // 4-aligned
    const int i4 = ib >> 2;                      // shared straddle index
    const float vi0 = v[ib + 0];
    const float vi1 = v[ib + 1];
    const float vi2 = v[ib + 2];
    const float vi3 = v[ib + 3];

    int c0 = 0, c1 = 0, c2 = 0, c3 = 0;
#pragma unroll 4
    for (int j4 = lane; j4 < NN / 4; j4 += 32) {
        float4 w = ((const float4*)v)[j4];
        if (j4 < i4) {
            c0 += (w.x >= vi0) + (w.y >= vi0) + (w.z >= vi0) + (w.w >= vi0);
            c1 += (w.x >= vi1) + (w.y >= vi1) + (w.z >= vi1) + (w.w >= vi1);
            c2 += (w.x >= vi2) + (w.y >= vi2) + (w.z >= vi2) + (w.w >= vi2);
            c3 += (w.x >= vi3) + (w.y >= vi3) + (w.z >= vi3) + (w.w >= vi3);
        } else if (j4 > i4) {
            c0 += (w.x > vi0) + (w.y > vi0) + (w.z > vi0) + (w.w > vi0);
            c1 += (w.x > vi1) + (w.y > vi1) + (w.z > vi1) + (w.w > vi1);
            c2 += (w.x > vi2) + (w.y > vi2) + (w.z > vi2) + (w.w > vi2);
            c3 += (w.x > vi3) + (w.y > vi3) + (w.z > vi3) + (w.w > vi3);
        } else {
            // straddling float4: w holds elements ib..ib+3 exactly
            int j = j4 * 4;
            c0 += ((w.x > vi0) || ((w.x == vi0) && (j + 0 < ib + 0)))
                + ((w.y > vi0) || ((w.y == vi0) && (j + 1 < ib + 0)))
                + ((w.z > vi0) || ((w.z == vi0) && (j + 2 < ib + 0)))
                + ((w.w > vi0) || ((w.w == vi0) && (j + 3 < ib + 0)));
            c1 += ((w.x > vi1) || ((w.x == vi1) && (j + 0 < ib + 1)))
                + ((w.y > vi1) || ((w.y == vi1) && (j + 1 < ib + 1)))
                + ((w.z > vi1) || ((w.z == vi1) && (j + 2 < ib + 1)))
                + ((w.w > vi1) || ((w.w == vi1) && (j + 3 < ib + 1)));
            c2 += ((w.x > vi2) || ((w.x == vi2) && (j + 0 < ib + 2)))
                + ((w.y > vi2) || ((w.y == vi2) && (j + 1 < ib + 2)))
                + ((w.z > vi2) || ((w.z == vi2) && (j + 2 < ib + 2)))
                + ((w.w > vi2) || ((w.w == vi2) && (j + 3 < ib + 2)));
            c3 += ((w.x > vi3) || ((w.x == vi3) && (j + 0 < ib + 3)))
                + ((w.y > vi3) || ((w.y == vi3) && (j + 1 < ib + 3)))
                + ((w.z > vi3) || ((w.z == vi3) && (j + 2 < ib + 3)))
                + ((w.w > vi3) || ((w.w == vi3) && (j + 3 < ib + 3)));
        }
    }
#pragma unroll
    for (int o = 16; o > 0; o >>= 1) {
        c0 += __shfl_xor_sync(0xffffffffu, c0, o);
        c1 += __shfl_xor_sync(0xffffffffu, c1, o);
        c2 += __shfl_xor_sync(0xffffffffu, c2, o);
        c3 += __shfl_xor_sync(0xffffffffu, c3, o);
    }

    if (lane == 0) {
        g_sel[b * NN + ib + 0] = (c0 < KK) ? 1 : 0;
        g_sel[b * NN + ib + 1] = (c1 < KK) ? 1 : 0;
        g_sel[b * NN + ib + 2] = (c2 < KK) ? 1 : 0;
        g_sel[b * NN + ib + 3] = (c3 < KK) ? 1 : 0;
    }
}

// ============================================================
// Kernel 3b: compaction via block scan
// ============================================================
__global__ __launch_bounds__(1024) void topk_compact_kernel()
{
    const int b = blockIdx.x;
    const int t = threadIdx.x;
    __shared__ int wsum[32];

    const int f0 = g_sel[b * NN + 2 * t];
    const int f1 = g_sel[b * NN + 2 * t + 1];
    const int mysum = f0 + f1;

    int inc = mysum;
#pragma unroll
    for (int o = 1; o < 32; o <<= 1) {
        int u = __shfl_up_sync(0xffffffffu, inc, o);
        if ((t & 31) >= o) inc += u;
    }
    if ((t & 31) == 31) wsum[t >> 5] = inc;
    __syncthreads();
    if (t < 32) {
        int wv = wsum[t];
#pragma unroll
        for (int o = 1; o < 32; o <<= 1) {
            int u = __shfl_up_sync(0xffffffffu, wv, o);
            if (t >= o) wv += u;
        }
        wsum[t] = wv;
    }
    __syncthreads();

    int excl = inc - mysum + ((t >> 5) ? wsum[(t >> 5) - 1] : 0);
    if (f0 && excl < KK)      g_topidx[b * KK + excl] = 2 * t;
    if (f1 && excl + f0 < KK) g_topidx[b * KK + excl + f0] = 2 * t + 1;
}

// ============================================================
// Kernel 4: rel top-R + soi triples; fully parallel scatter
// ============================================================
__global__ __launch_bounds__(128) void rel_kernel(
    const float* __restrict__ scores, float* __restrict__ soi_out)
{
    const int b  = blockIdx.y;
    const int tI = blockIdx.x;
    __shared__ float r[KK];
    __shared__ unsigned char sel[KK];

    const int ti = g_topidx[b * KK + tI];
    const int t  = threadIdx.x;

    if (t < KK) {
        int tj = g_topidx[b * KK + t];
        float val = scores[((size_t)b * NN + ti) * NN + tj];
        r[t] = (t == tI) ? BIGV : val;
    }
    __syncthreads();

    if (t < KK) {
        float vi = r[t];
        int cnt = 0;
#pragma unroll 4
        for (int j = 0; j < KK; j++) {
            float vj = r[j];
            cnt += (vj > vi) || ((vj == vi) && (j < t));
        }
        sel[t] = (cnt < RR) ? 1 : 0;
    }
    __syncthreads();

    if (t < KK && sel[t]) {
        int pos = 0;
#pragma unroll 4
        for (int j = 0; j < KK; j++) pos += (j < t) ? sel[j] : 0;
        if (pos < RR) {
            int obj = g_topidx[b * KK + t];
            int p = (b * KK + tI) * RR + pos;
            g_pairs[2 * p]     = ti;
            g_pairs[2 * p + 1] = obj;
            size_t so = (size_t)p * 3;
            soi_out[so + 0] = (float)b;
            soi_out[so + 1] = (float)ti;
            soi_out[so + 2] = (float)obj;
        }
    }
}

// ============================================================
// Kernel 5: re = LayerNorm(q[b,subj] + q[b,obj])
// ============================================================
__global__ __launch_bounds__(256) void re_kernel(
    const float* __restrict__ q, float* __restrict__ re_out)
{
    const int warp = threadIdx.x >> 5;
    const int lane = threadIdx.x & 31;
    const int p = blockIdx.x * 8 + warp;
    if (p >= BB * KK * RR) return;

    const int b = p / (KK * RR);
    const int subj = g_pairs[2 * p];
    const int obj  = g_pairs[2 * p + 1];
    const float4* qs = (const float4*)(q + ((size_t)b * NN + subj) * DD);
    const float4* qo = (const float4*)(q + ((size_t)b * NN + obj)  * DD);

    float x[8];
    float s = 0.0f, s2 = 0.0f;
#pragma unroll
    for (int c = 0; c < 2; c++) {
        float4 a = qs[lane + 32 * c];
        float4 o = qo[lane + 32 * c];
        x[4 * c + 0] = a.x + o.x; x[4 * c + 1] = a.y + o.y;
        x[4 * c + 2] = a.z + o.z; x[4 * c + 3] = a.w + o.w;
    }
#pragma unroll
    for (int e = 0; e < 8; e++) { s += x[e]; s2 += x[e] * x[e]; }
#pragma unroll
    for (int o = 16; o > 0; o >>= 1) {
        s  += __shfl_xor_sync(0xffffffffu, s,  o);
        s2 += __shfl_xor_sync(0xffffffffu, s2, o);
    }
    const float mu  = s * (1.0f / DD);
    const float var = s2 * (1.0f / DD) - mu * mu;
    const float inv = rsqrtf(var + LN_EPS);

    float4* dst = (float4*)(re_out + (size_t)p * DD);
#pragma unroll
    for (int c = 0; c < 2; c++) {
        float4 r;
        r.x = (x[4 * c + 0] - mu) * inv;
        r.y = (x[4 * c + 1] - mu) * inv;
        r.z = (x[4 * c + 2] - mu) * inv;
        r.w = (x[4 * c + 3] - mu) * inv;
        dst[lane + 32 * c] = r;
    }
}

// ============================================================
extern "C" void kernel_launch(void* const* d_in, const int* in_sizes, int n_in,
                              void* d_out, int out_size)
{
    const float* q = (const float*)d_in[0];
    const float* k = (const float*)d_in[1];

    float* scores = (float*)d_out;
    float* soi    = scores + (size_t)BB * NN * NN;
    float* re     = soi + (size_t)BB * KK * RR * 3;

    void *qs_ptr = nullptr, *ks_ptr = nullptr;
    cudaGetSymbolAddress(&qs_ptr, g_qsb);
    cudaGetSymbolAddress(&ks_ptr, g_ksb);

    cudaFuncSetAttribute(gemm_bf16k, cudaFuncAttributeMaxDynamicSharedMemorySize, SMEM_BYTES);

    split3b_kernel<<<dim3(BB * NN * DD / 8 / 256, 2), 256>>>(q, k);
    gemm_bf16k<<<dim3(NN / BN, NN / BM, BB), 256, SMEM_BYTES>>>(
        (const __nv_bfloat16*)qs_ptr, (const __nv_bfloat16*)ks_ptr, scores);
    softmax_kernel<<<BB * NN / 2, 256>>>(scores);
    topk_count_kernel<<<dim3(NN / 32, BB), 256>>>();
    topk_compact_kernel<<<BB, 1024>>>();
    rel_kernel<<<dim3(KK, BB), 128>>>(scores, soi);
    re_kernel<<<(BB * KK * RR + 7) / 8, 256>>>(q, re);
}

// round 16
// speedup vs baseline: 1.0931x; 1.0090x over previous
#include <cuda_runtime.h>
#include <cuda_bf16.h>
#include <cstdint>

#define BB 8
#define NN 2048
#define DD 256
#define K3 768            // 3-term split K' = 3*DD (bf16)
#define KK 100
#define RR 5
#define BIGV 1000000000.0f
#define LN_EPS 1e-5f
#define ESHIFT 48.0f

// GEMM tiling
#define BM 128
#define BN 128
#define BKE 64                         // bf16 elems per stage (128 B/row)
#define PADB 72                        // padded row stride in bf16 elems
#define STAGE_H (2 * BM * PADB)        // halves per stage (A+B) = 18432
#define NSTG 3
#define SMEM_BYTES (NSTG * STAGE_H * 2)   // 110592

// ---- scratch (device globals; no allocations allowed) ----
__device__ __align__(128) __nv_bfloat16 g_qsb[(size_t)BB * NN * K3];
__device__ __align__(128) __nv_bfloat16 g_ksb[(size_t)BB * NN * K3];
__device__ float g_diag[BB * NN];
__device__ int   g_sel[BB * NN];
__device__ int   g_topidx[BB * KK];

// ============================================================
// helpers
// ============================================================
__device__ __forceinline__ void ldsm4(unsigned& r0, unsigned& r1, unsigned& r2, unsigned& r3,
                                      unsigned addr) {
    asm volatile("ldmatrix.sync.aligned.m8n8.x4.shared.b16 {%0,%1,%2,%3}, [%4];"
                 : "=r"(r0), "=r"(r1), "=r"(r2), "=r"(r3) : "r"(addr));
}
__device__ __forceinline__ void mma_bf16(float* d, const unsigned* a, const unsigned* b) {
    asm volatile("mma.sync.aligned.m16n8k16.row.col.f32.bf16.bf16.f32 "
                 "{%0,%1,%2,%3},{%4,%5,%6,%7},{%8,%9},{%0,%1,%2,%3};"
                 : "+f"(d[0]), "+f"(d[1]), "+f"(d[2]), "+f"(d[3])
                 : "r"(a[0]), "r"(a[1]), "r"(a[2]), "r"(a[3]), "r"(b[0]), "r"(b[1]));
}
__device__ __forceinline__ void cpa16(void* smem_dst, const void* gsrc) {
    unsigned d = (unsigned)__cvta_generic_to_shared(smem_dst);
    asm volatile("cp.async.cg.shared.global [%0], [%1], 16;" :: "r"(d), "l"(gsrc));
}

// ============================================================
// Kernel 0: bf16 3-term split.  q -> [qh,qh,ql] ; k -> [kh,kl,kh]
// ============================================================
__global__ __launch_bounds__(256) void split3b_kernel(
    const float* __restrict__ q, const float* __restrict__ k)
{
    const bool isK = blockIdx.y != 0;
    const float4* src = (const float4*)(isK ? k : q);
    __nv_bfloat16* dst = isK ? g_ksb : g_qsb;
    size_t i = (size_t)blockIdx.x * 256 + threadIdx.x;

    float4 v0 = src[2 * i];
    float4 v1 = src[2 * i + 1];
    float xs[8] = {v0.x, v0.y, v0.z, v0.w, v1.x, v1.y, v1.z, v1.w};

    __align__(16) __nv_bfloat16 out[24];
#pragma unroll
    for (int e = 0; e < 8; e++) {
        __nv_bfloat16 h = __float2bfloat16(xs[e]);
        __nv_bfloat16 l = __float2bfloat16(xs[e] - __bfloat162float(h));
        if (!isK) { out[3 * e] = h; out[3 * e + 1] = h; out[3 * e + 2] = l; }
        else      { out[3 * e] = h; out[3 * e + 1] = l; out[3 * e + 2] = h; }
    }
    uint4* o = (uint4*)(dst + 24 * i);
    o[0] = ((uint4*)out)[0];
    o[1] = ((uint4*)out)[1];
    o[2] = ((uint4*)out)[2];
}

// ============================================================
// Kernel 1: bf16 mma.sync m16n8k16 GEMM over K'=768
// 3-stage cp.async pipeline, ONE __syncthreads per iteration
// ============================================================
__global__ __launch_bounds__(256, 2) void gemm_bf16k(
    const __nv_bfloat16* __restrict__ A0, const __nv_bfloat16* __restrict__ B0,
    float* __restrict__ out)
{
    extern __shared__ __nv_bfloat16 sm[];
    const int b = blockIdx.z;
    const int row0 = blockIdx.y * BM;
    const int col0 = blockIdx.x * BN;
    const __nv_bfloat16* A  = A0 + (size_t)b * NN * K3;
    const __nv_bfloat16* Bm = B0 + (size_t)b * NN * K3;
    float* C = out + (size_t)b * NN * NN;

    const int tid = threadIdx.x;
    const int warp = tid >> 5, lane = tid & 31;
    const int wm = (warp >> 2) * 64;
    const int wn = (warp & 3) * 32;

    float acc[4][4][4];
#pragma unroll
    for (int mf = 0; mf < 4; mf++)
#pragma unroll
        for (int nf = 0; nf < 4; nf++)
#pragma unroll
            for (int e = 0; e < 4; e++) acc[mf][nf][e] = 0.0f;

#define LOAD_STAGE(s, kt)                                                      \
    do {                                                                       \
        __nv_bfloat16* As_ = sm + (s) * STAGE_H;                               \
        __nv_bfloat16* Bs_ = As_ + BM * PADB;                                  \
        _Pragma("unroll")                                                      \
        for (int l = 0; l < 4; l++) {                                          \
            int idx = tid + l * 256;                                           \
            int row = idx >> 3;                                                \
            int ce  = (idx & 7) * 8;                                           \
            cpa16(&As_[row * PADB + ce], &A [(size_t)(row0 + row) * K3 + (kt) + ce]); \
            cpa16(&Bs_[row * PADB + ce], &Bm[(size_t)(col0 + row) * K3 + (kt) + ce]); \
        }                                                                      \
        asm volatile("cp.async.commit_group;");                                \
    } while (0)

    LOAD_STAGE(0, 0);
    LOAD_STAGE(1, BKE);

    const int NT = K3 / BKE;   // 12
    int cur = 0, nxt = 2;
    for (int t = 0; t < NT; t++) {
        if (t < NT - 1) { asm volatile("cp.async.wait_group 1;"); }
        else            { asm volatile("cp.async.wait_group 0;"); }
        __syncthreads();

        if (t + 2 < NT) {
            LOAD_STAGE(nxt, (t + 2) * BKE);
        }

        const __nv_bfloat16* As_ = sm + cur * STAGE_H;
        const __nv_bfloat16* Bs_ = As_ + BM * PADB;

#pragma unroll
        for (int kk = 0; kk < 4; kk++) {
            const int kb = kk * 16;

            unsigned a[4][4];
#pragma unroll
            for (int mf = 0; mf < 4; mf++) {
                int arow = wm + mf * 16 + (lane & 15);
                int acol = kb + ((lane >> 4) << 3);
                unsigned addr = (unsigned)__cvta_generic_to_shared(&As_[arow * PADB + acol]);
                ldsm4(a[mf][0], a[mf][1], a[mf][2], a[mf][3], addr);
            }
            unsigned bf[4][2];
#pragma unroll
            for (int half = 0; half < 2; half++) {
                int brow = wn + half * 16 + (lane & 7) + ((lane >> 4) << 3);
                int bcol = kb + (((lane >> 3) & 1) << 3);
                unsigned addr = (unsigned)__cvta_generic_to_shared(&Bs_[brow * PADB + bcol]);
                ldsm4(bf[half * 2][0], bf[half * 2][1],
                      bf[half * 2 + 1][0], bf[half * 2 + 1][1], addr);
            }
#pragma unroll
            for (int mf = 0; mf < 4; mf++)
#pragma unroll
                for (int nf = 0; nf < 4; nf++)
                    mma_bf16(acc[mf][nf], a[mf], bf[nf]);
        }

        cur = (cur == 2) ? 0 : cur + 1;
        nxt = (nxt == 2) ? 0 : nxt + 1;
    }
#undef LOAD_STAGE

#pragma unroll
    for (int mf = 0; mf < 4; mf++)
#pragma unroll
        for (int nf = 0; nf < 4; nf++) {
            int r0 = row0 + wm + mf * 16 + (lane >> 2);
            int c0 = col0 + wn + nf * 8 + (lane & 3) * 2;
            *(float2*)&C[(size_t)r0 * NN + c0] =
                make_float2(acc[mf][nf][0], acc[mf][nf][1]);
            *(float2*)&C[(size_t)(r0 + 8) * NN + c0] =
                make_float2(acc[mf][nf][2], acc[mf][nf][3]);
        }
}

// ============================================================
// Kernel 2: softmax without max pass (constant shift 48).
// TWO rows per block; reversed block->row mapping (L2 tail chase)
// ============================================================
__global__ __launch_bounds__(256) void softmax_kernel(float* __restrict__ scores)
{
    const int rowg0 = (gridDim.x - 1 - blockIdx.x) * 2;   // reversed mapping
    const int i0 = rowg0 & (NN - 1);
    const int i1 = (rowg0 + 1) & (NN - 1);
    float* rowA = scores + (size_t)rowg0 * NN;
    float* rowB = rowA + NN;
    const int t = threadIdx.x;

    float4 a0 = ((float4*)rowA)[t];
    float4 a1 = ((float4*)rowA)[t + 256];
    float4 b0 = ((float4*)rowB)[t];
    float4 b1 = ((float4*)rowB)[t + 256];

    a0.x = __expf(a0.x - ESHIFT); a0.y = __expf(a0.y - ESHIFT);
    a0.z = __expf(a0.z - ESHIFT); a0.w = __expf(a0.w - ESHIFT);
    a1.x = __expf(a1.x - ESHIFT); a1.y = __expf(a1.y - ESHIFT);
    a1.z = __expf(a1.z - ESHIFT); a1.w = __expf(a1.w - ESHIFT);
    b0.x = __expf(b0.x - ESHIFT); b0.y = __expf(b0.y - ESHIFT);
    b0.z = __expf(b0.z - ESHIFT); b0.w = __expf(b0.w - ESHIFT);
    b1.x = __expf(b1.x - ESHIFT); b1.y = __expf(b1.y - ESHIFT);
    b1.z = __expf(b1.z - ESHIFT); b1.w = __expf(b1.w - ESHIFT);

    float sa = a0.x + a0.y + a0.z + a0.w + a1.x + a1.y + a1.z + a1.w;
    float sb = b0.x + b0.y + b0.z + b0.w + b1.x + b1.y + b1.z + b1.w;

    __shared__ float redA[8], redB[8];
#pragma unroll
    for (int o = 16; o > 0; o >>= 1) {
        sa += __shfl_xor_sync(0xffffffffu, sa, o);
        sb += __shfl_xor_sync(0xffffffffu, sb, o);
    }
    if ((t & 31) == 0) { redA[t >> 5] = sa; redB[t >> 5] = sb; }
    __syncthreads();
    float bsA = 0.0f, bsB = 0.0f;
#pragma unroll
    for (int w = 0; w < 8; w++) { bsA += redA[w]; bsB += redB[w]; }

    const float invA = 1.0f / bsA;
    const float invB = 1.0f / bsB;
    a0.x *= invA; a0.y *= invA; a0.z *= invA; a0.w *= invA;
    a1.x *= invA; a1.y *= invA; a1.z *= invA; a1.w *= invA;
    b0.x *= invB; b0.y *= invB; b0.z *= invB; b0.w *= invB;
    b1.x *= invB; b1.y *= invB; b1.z *= invB; b1.w *= invB;

    ((float4*)rowA)[t]       = a0;
    ((float4*)rowA)[t + 256] = a1;
    ((float4*)rowB)[t]       = b0;
    ((float4*)rowB)[t + 256] = b1;

    {
        int c0 = i0 >> 2, cc = i0 & 3;
        if (c0 == t) {
            float d = (cc == 0) ? a0.x : (cc == 1) ? a0.y : (cc == 2) ? a0.z : a0.w;
            g_diag[rowg0] = d;
        } else if (c0 == t + 256) {
            float d = (cc == 0) ? a1.x : (cc == 1) ? a1.y : (cc == 2) ? a1.z : a1.w;
            g_diag[rowg0] = d;
        }
    }
    {
        int c0 = i1 >> 2, cc = i1 & 3;
        if (c0 == t) {
            float d = (cc == 0) ? b0.x : (cc == 1) ? b0.y : (cc == 2) ? b0.z : b0.w;
            g_diag[rowg0 + 1] = d;
        } else if (c0 == t + 256) {
            float d = (cc == 0) ? b1.x : (cc == 1) ? b1.y : (cc == 2) ? b1.z : b1.w;
            g_diag[rowg0 + 1] = d;
        }
    }
}

// ============================================================
// Kernel 3a: rank counting — one warp per TWO consecutive
// elements (ib 2-aligned: both share the straddling float4).
// grid (NN/16, BB) = (128, 8), block 256 (8 warps x 2 elems).
// ============================================================
__global__ __launch_bounds__(256) void topk_count_kernel()
{
    const int b = blockIdx.y;
    __shared__ __align__(16) float v[NN];

    for (int i = threadIdx.x; i < NN / 4; i += 256)
        ((float4*)v)[i] = ((const float4*)(g_diag + b * NN))[i];
    __syncthreads();

    const int warp = threadIdx.x >> 5;
    const int lane = threadIdx.x & 31;
    const int ib = blockIdx.x * 16 + warp * 2;   // 2-aligned
    const int i4 = ib >> 2;                      // shared straddle index
    const float vi0 = v[ib + 0];
    const float vi1 = v[ib + 1];

    int c0 = 0, c1 = 0;
#pragma unroll 4
    for (int j4 = lane; j4 < NN / 4; j4 += 32) {
        float4 w = ((const float4*)v)[j4];
        if (j4 < i4) {
            c0 += (w.x >= vi0) + (w.y >= vi0) + (w.z >= vi0) + (w.w >= vi0);
            c1 += (w.x >= vi1) + (w.y >= vi1) + (w.z >= vi1) + (w.w >= vi1);
        } else if (j4 > i4) {
            c0 += (w.x > vi0) + (w.y > vi0) + (w.z > vi0) + (w.w > vi0);
            c1 += (w.x > vi1) + (w.y > vi1) + (w.z > vi1) + (w.w > vi1);
        } else {
            int j = j4 * 4;
            c0 += ((w.x > vi0) || ((w.x == vi0) && (j + 0 < ib + 0)))
                + ((w.y > vi0) || ((w.y == vi0) && (j + 1 < ib + 0)))
                + ((w.z > vi0) || ((w.z == vi0) && (j + 2 < ib + 0)))
                + ((w.w > vi0) || ((w.w == vi0) && (j + 3 < ib + 0)));
            c1 += ((w.x > vi1) || ((w.x == vi1) && (j + 0 < ib + 1)))
                + ((w.y > vi1) || ((w.y == vi1) && (j + 1 < ib + 1)))
                + ((w.z > vi1) || ((w.z == vi1) && (j + 2 < ib + 1)))
                + ((w.w > vi1) || ((w.w == vi1) && (j + 3 < ib + 1)));
        }
    }
#pragma unroll
    for (int o = 16; o > 0; o >>= 1) {
        c0 += __shfl_xor_sync(0xffffffffu, c0, o);
        c1 += __shfl_xor_sync(0xffffffffu, c1, o);
    }

    if (lane == 0) {
        g_sel[b * NN + ib + 0] = (c0 < KK) ? 1 : 0;
        g_sel[b * NN + ib + 1] = (c1 < KK) ? 1 : 0;
    }
}

// ============================================================
// Kernel 3b: compaction via block scan
// ============================================================
__global__ __launch_bounds__(1024) void topk_compact_kernel()
{
    const int b = blockIdx.x;
    const int t = threadIdx.x;
    __shared__ int wsum[32];

    const int f0 = g_sel[b * NN + 2 * t];
    const int f1 = g_sel[b * NN + 2 * t + 1];
    const int mysum = f0 + f1;

    int inc = mysum;
#pragma unroll
    for (int o = 1; o < 32; o <<= 1) {
        int u = __shfl_up_sync(0xffffffffu, inc, o);
        if ((t & 31) >= o) inc += u;
    }
    if ((t & 31) == 31) wsum[t >> 5] = inc;
    __syncthreads();
    if (t < 32) {
        int wv = wsum[t];
#pragma unroll
        for (int o = 1; o < 32; o <<= 1) {
            int u = __shfl_up_sync(0xffffffffu, wv, o);
            if (t >= o) wv += u;
        }
        wsum[t] = wv;
    }
    __syncthreads();

    int excl = inc - mysum + ((t >> 5) ? wsum[(t >> 5) - 1] : 0);
    if (f0 && excl < KK)      g_topidx[b * KK + excl] = 2 * t;
    if (f1 && excl + f0 < KK) g_topidx[b * KK + excl + f0] = 2 * t + 1;
}

// ============================================================
// Kernel 4: FUSED rel top-R + soi + LayerNorm(re).
// 160 threads: phase 1 = gather/count/scatter (threads < 100),
// phase 2 = 5 warps, one LayerNorm'd pair each.
// ============================================================
__global__ __launch_bounds__(160) void rel_re_kernel(
    const float* __restrict__ scores, const float* __restrict__ q,
    float* __restrict__ soi_out, float* __restrict__ re_out)
{
    const int b  = blockIdx.y;
    const int tI = blockIdx.x;
    __shared__ float r[KK];
    __shared__ unsigned char sel[KK];
    __shared__ int sobj[RR];

    const int ti = g_topidx[b * KK + tI];
    const int t  = threadIdx.x;

    if (t < KK) {
        int tj = g_topidx[b * KK + t];
        float val = scores[((size_t)b * NN + ti) * NN + tj];
        r[t] = (t == tI) ? BIGV : val;
    }
    __syncthreads();

    if (t < KK) {
        float vi = r[t];
        int cnt = 0;
#pragma unroll 4
        for (int j = 0; j < KK; j++) {
            float vj = r[j];
            cnt += (vj > vi) || ((vj == vi) && (j < t));
        }
        sel[t] = (cnt < RR) ? 1 : 0;
    }
    __syncthreads();

    if (t < KK && sel[t]) {
        int pos = 0;
#pragma unroll 4
        for (int j = 0; j < KK; j++) pos += (j < t) ? sel[j] : 0;
        if (pos < RR) {
            int obj = g_topidx[b * KK + t];
            sobj[pos] = obj;
            int p = (b * KK + tI) * RR + pos;
            size_t so = (size_t)p * 3;
            soi_out[so + 0] = (float)b;
            soi_out[so + 1] = (float)ti;
            soi_out[so + 2] = (float)obj;
        }
    }
    __syncthreads();

    // phase 2: warp w computes re for pair w (exactly RR=5 warps)
    const int w = t >> 5;
    const int lane = t & 31;
    const int obj = sobj[w];
    const float4* qs = (const float4*)(q + ((size_t)b * NN + ti)  * DD);
    const float4* qo = (const float4*)(q + ((size_t)b * NN + obj) * DD);

    float x[8];
    float s = 0.0f, s2 = 0.0f;
#pragma unroll
    for (int c = 0; c < 2; c++) {
        float4 a = qs[lane + 32 * c];
        float4 o = qo[lane + 32 * c];
        x[4 * c + 0] = a.x + o.x; x[4 * c + 1] = a.y + o.y;
        x[4 * c + 2] = a.z + o.z; x[4 * c + 3] = a.w + o.w;
    }
#pragma unroll
    for (int e = 0; e < 8; e++) { s += x[e]; s2 += x[e] * x[e]; }
#pragma unroll
    for (int o = 16; o > 0; o >>= 1) {
        s  += __shfl_xor_sync(0xffffffffu, s,  o);
        s2 += __shfl_xor_sync(0xffffffffu, s2, o);
    }
    const float mu  = s * (1.0f / DD);
    const float var = s2 * (1.0f / DD) - mu * mu;
    const float inv = rsqrtf(var + LN_EPS);

    const int p = (b * KK + tI) * RR + w;
    float4* dst = (float4*)(re_out + (size_t)p * DD);
#pragma unroll
    for (int c = 0; c < 2; c++) {
        float4 rr;
        rr.x = (x[4 * c + 0] - mu) * inv;
        rr.y = (x[4 * c + 1] - mu) * inv;
        rr.z = (x[4 * c + 2] - mu) * inv;
        rr.w = (x[4 * c + 3] - mu) * inv;
        dst[lane + 32 * c] = rr;
    }
}

// ============================================================
extern "C" void kernel_launch(void* const* d_in, const int* in_sizes, int n_in,
                              void* d_out, int out_size)
{
    const float* q = (const float*)d_in[0];
    const float* k = (const float*)d_in[1];

    float* scores = (float*)d_out;
    float* soi    = scores + (size_t)BB * NN * NN;
    float* re     = soi + (size_t)BB * KK * RR * 3;

    void *qs_ptr = nullptr, *ks_ptr = nullptr;
    cudaGetSymbolAddress(&qs_ptr, g_qsb);
    cudaGetSymbolAddress(&ks_ptr, g_ksb);

    cudaFuncSetAttribute(gemm_bf16k, cudaFuncAttributeMaxDynamicSharedMemorySize, SMEM_BYTES);

    split3b_kernel<<<dim3(BB * NN * DD / 8 / 256, 2), 256>>>(q, k);
    gemm_bf16k<<<dim3(NN / BN, NN / BM, BB), 256, SMEM_BYTES>>>(
        (const __nv_bfloat16*)qs_ptr, (const __nv_bfloat16*)ks_ptr, scores);
    softmax_kernel<<<BB * NN / 2, 256>>>(scores);
    topk_count_kernel<<<dim3(NN / 16, BB), 256>>>();
    topk_compact_kernel<<<BB, 1024>>>();
    rel_re_kernel<<<dim3(KK, BB), 160>>>(scores, q, soi, re);
}

// round 17
// speedup vs baseline: 1.0950x; 1.0018x over previous
#include <cuda_runtime.h>
#include <cuda_bf16.h>
#include <cstdint>

#define BB 8
#define NN 2048
#define DD 256
#define K3 768            // 3-term split K' = 3*DD (bf16)
#define KK 100
#define RR 5
#define BIGV 1000000000.0f
#define LN_EPS 1e-5f
#define ESHIFT 48.0f

// GEMM tiling
#define BM 128
#define BN 128
#define BKE 64                         // bf16 elems per stage (128 B/row)
#define PADB 72                        // padded row stride in bf16 elems
#define STAGE_H (2 * BM * PADB)        // halves per stage (A+B) = 18432
#define NSTG 3
#define SMEM_BYTES (NSTG * STAGE_H * 2)   // 110592

// ---- scratch (device globals; no allocations allowed) ----
__device__ __align__(128) __nv_bfloat16 g_qsb[(size_t)BB * NN * K3];
__device__ __align__(128) __nv_bfloat16 g_ksb[(size_t)BB * NN * K3];
__device__ float g_diag[BB * NN];
__device__ int   g_sel[BB * NN];
__device__ int   g_topidx[BB * KK];
__device__ int   g_ticket[BB];        // zero-initialized; reset by last block

// ============================================================
// helpers
// ============================================================
__device__ __forceinline__ void ldsm4(unsigned& r0, unsigned& r1, unsigned& r2, unsigned& r3,
                                      unsigned addr) {
    asm volatile("ldmatrix.sync.aligned.m8n8.x4.shared.b16 {%0,%1,%2,%3}, [%4];"
                 : "=r"(r0), "=r"(r1), "=r"(r2), "=r"(r3) : "r"(addr));
}
__device__ __forceinline__ void mma_bf16(float* d, const unsigned* a, const unsigned* b) {
    asm volatile("mma.sync.aligned.m16n8k16.row.col.f32.bf16.bf16.f32 "
                 "{%0,%1,%2,%3},{%4,%5,%6,%7},{%8,%9},{%0,%1,%2,%3};"
                 : "+f"(d[0]), "+f"(d[1]), "+f"(d[2]), "+f"(d[3])
                 : "r"(a[0]), "r"(a[1]), "r"(a[2]), "r"(a[3]), "r"(b[0]), "r"(b[1]));
}
__device__ __forceinline__ void cpa16(void* smem_dst, const void* gsrc) {
    unsigned d = (unsigned)__cvta_generic_to_shared(smem_dst);
    asm volatile("cp.async.cg.shared.global [%0], [%1], 16;" :: "r"(d), "l"(gsrc));
}

// ============================================================
// Kernel 0: bf16 3-term split.  q -> [qh,qh,ql] ; k -> [kh,kl,kh]
// ============================================================
__global__ __launch_bounds__(256) void split3b_kernel(
    const float* __restrict__ q, const float* __restrict__ k)
{
    const bool isK = blockIdx.y != 0;
    const float4* src = (const float4*)(isK ? k : q);
    __nv_bfloat16* dst = isK ? g_ksb : g_qsb;
    size_t i = (size_t)blockIdx.x * 256 + threadIdx.x;

    float4 v0 = src[2 * i];
    float4 v1 = src[2 * i + 1];
    float xs[8] = {v0.x, v0.y, v0.z, v0.w, v1.x, v1.y, v1.z, v1.w};

    __align__(16) __nv_bfloat16 out[24];
#pragma unroll
    for (int e = 0; e < 8; e++) {
        __nv_bfloat16 h = __float2bfloat16(xs[e]);
        __nv_bfloat16 l = __float2bfloat16(xs[e] - __bfloat162float(h));
        if (!isK) { out[3 * e] = h; out[3 * e + 1] = h; out[3 * e + 2] = l; }
        else      { out[3 * e] = h; out[3 * e + 1] = l; out[3 * e + 2] = h; }
    }
    uint4* o = (uint4*)(dst + 24 * i);
    o[0] = ((uint4*)out)[0];
    o[1] = ((uint4*)out)[1];
    o[2] = ((uint4*)out)[2];
}

// ============================================================
// Kernel 1: bf16 mma.sync m16n8k16 GEMM over K'=768
// 3-stage cp.async pipeline, ONE __syncthreads per iteration
// ============================================================
__global__ __launch_bounds__(256, 2) void gemm_bf16k(
    const __nv_bfloat16* __restrict__ A0, const __nv_bfloat16* __restrict__ B0,
    float* __restrict__ out)
{
    extern __shared__ __nv_bfloat16 sm[];
    const int b = blockIdx.z;
    const int row0 = blockIdx.y * BM;
    const int col0 = blockIdx.x * BN;
    const __nv_bfloat16* A  = A0 + (size_t)b * NN * K3;
    const __nv_bfloat16* Bm = B0 + (size_t)b * NN * K3;
    float* C = out + (size_t)b * NN * NN;

    const int tid = threadIdx.x;
    const int warp = tid >> 5, lane = tid & 31;
    const int wm = (warp >> 2) * 64;
    const int wn = (warp & 3) * 32;

    float acc[4][4][4];
#pragma unroll
    for (int mf = 0; mf < 4; mf++)
#pragma unroll
        for (int nf = 0; nf < 4; nf++)
#pragma unroll
            for (int e = 0; e < 4; e++) acc[mf][nf][e] = 0.0f;

#define LOAD_STAGE(s, kt)                                                      \
    do {                                                                       \
        __nv_bfloat16* As_ = sm + (s) * STAGE_H;                               \
        __nv_bfloat16* Bs_ = As_ + BM * PADB;                                  \
        _Pragma("unroll")                                                      \
        for (int l = 0; l < 4; l++) {                                          \
            int idx = tid + l * 256;                                           \
            int row = idx >> 3;                                                \
            int ce  = (idx & 7) * 8;                                           \
            cpa16(&As_[row * PADB + ce], &A [(size_t)(row0 + row) * K3 + (kt) + ce]); \
            cpa16(&Bs_[row * PADB + ce], &Bm[(size_t)(col0 + row) * K3 + (kt) + ce]); \
        }                                                                      \
        asm volatile("cp.async.commit_group;");                                \
    } while (0)

    LOAD_STAGE(0, 0);
    LOAD_STAGE(1, BKE);

    const int NT = K3 / BKE;   // 12
    int cur = 0, nxt = 2;
    for (int t = 0; t < NT; t++) {
        if (t < NT - 1) { asm volatile("cp.async.wait_group 1;"); }
        else            { asm volatile("cp.async.wait_group 0;"); }
        __syncthreads();

        if (t + 2 < NT) {
            LOAD_STAGE(nxt, (t + 2) * BKE);
        }

        const __nv_bfloat16* As_ = sm + cur * STAGE_H;
        const __nv_bfloat16* Bs_ = As_ + BM * PADB;

#pragma unroll
        for (int kk = 0; kk < 4; kk++) {
            const int kb = kk * 16;

            unsigned a[4][4];
#pragma unroll
            for (int mf = 0; mf < 4; mf++) {
                int arow = wm + mf * 16 + (lane & 15);
                int acol = kb + ((lane >> 4) << 3);
                unsigned addr = (unsigned)__cvta_generic_to_shared(&As_[arow * PADB + acol]);
                ldsm4(a[mf][0], a[mf][1], a[mf][2], a[mf][3], addr);
            }
            unsigned bf[4][2];
#pragma unroll
            for (int half = 0; half < 2; half++) {
                int brow = wn + half * 16 + (lane & 7) + ((lane >> 4) << 3);
                int bcol = kb + (((lane >> 3) & 1) << 3);
                unsigned addr = (unsigned)__cvta_generic_to_shared(&Bs_[brow * PADB + bcol]);
                ldsm4(bf[half * 2][0], bf[half * 2][1],
                      bf[half * 2 + 1][0], bf[half * 2 + 1][1], addr);
            }
#pragma unroll
            for (int mf = 0; mf < 4; mf++)
#pragma unroll
                for (int nf = 0; nf < 4; nf++)
                    mma_bf16(acc[mf][nf], a[mf], bf[nf]);
        }

        cur = (cur == 2) ? 0 : cur + 1;
        nxt = (nxt == 2) ? 0 : nxt + 1;
    }
#undef LOAD_STAGE

#pragma unroll
    for (int mf = 0; mf < 4; mf++)
#pragma unroll
        for (int nf = 0; nf < 4; nf++) {
            int r0 = row0 + wm + mf * 16 + (lane >> 2);
            int c0 = col0 + wn + nf * 8 + (lane & 3) * 2;
            *(float2*)&C[(size_t)r0 * NN + c0] =
                make_float2(acc[mf][nf][0], acc[mf][nf][1]);
            *(float2*)&C[(size_t)(r0 + 8) * NN + c0] =
                make_float2(acc[mf][nf][2], acc[mf][nf][3]);
        }
}

// ============================================================
// Kernel 2: softmax without max pass (constant shift 48).
// TWO rows per block; reversed block->row mapping (L2 tail chase)
// ============================================================
__global__ __launch_bounds__(256) void softmax_kernel(float* __restrict__ scores)
{
    const int rowg0 = (gridDim.x - 1 - blockIdx.x) * 2;   // reversed mapping
    const int i0 = rowg0 & (NN - 1);
    const int i1 = (rowg0 + 1) & (NN - 1);
    float* rowA = scores + (size_t)rowg0 * NN;
    float* rowB = rowA + NN;
    const int t = threadIdx.x;

    float4 a0 = ((float4*)rowA)[t];
    float4 a1 = ((float4*)rowA)[t + 256];
    float4 b0 = ((float4*)rowB)[t];
    float4 b1 = ((float4*)rowB)[t + 256];

    a0.x = __expf(a0.x - ESHIFT); a0.y = __expf(a0.y - ESHIFT);
    a0.z = __expf(a0.z - ESHIFT); a0.w = __expf(a0.w - ESHIFT);
    a1.x = __expf(a1.x - ESHIFT); a1.y = __expf(a1.y - ESHIFT);
    a1.z = __expf(a1.z - ESHIFT); a1.w = __expf(a1.w - ESHIFT);
    b0.x = __expf(b0.x - ESHIFT); b0.y = __expf(b0.y - ESHIFT);
    b0.z = __expf(b0.z - ESHIFT); b0.w = __expf(b0.w - ESHIFT);
    b1.x = __expf(b1.x - ESHIFT); b1.y = __expf(b1.y - ESHIFT);
    b1.z = __expf(b1.z - ESHIFT); b1.w = __expf(b1.w - ESHIFT);

    float sa = a0.x + a0.y + a0.z + a0.w + a1.x + a1.y + a1.z + a1.w;
    float sb = b0.x + b0.y + b0.z + b0.w + b1.x + b1.y + b1.z + b1.w;

    __shared__ float redA[8], redB[8];
#pragma unroll
    for (int o = 16; o > 0; o >>= 1) {
        sa += __shfl_xor_sync(0xffffffffu, sa, o);
        sb += __shfl_xor_sync(0xffffffffu, sb, o);
    }
    if ((t & 31) == 0) { redA[t >> 5] = sa; redB[t >> 5] = sb; }
    __syncthreads();
    float bsA = 0.0f, bsB = 0.0f;
#pragma unroll
    for (int w = 0; w < 8; w++) { bsA += redA[w]; bsB += redB[w]; }

    const float invA = 1.0f / bsA;
    const float invB = 1.0f / bsB;
    a0.x *= invA; a0.y *= invA; a0.z *= invA; a0.w *= invA;
    a1.x *= invA; a1.y *= invA; a1.z *= invA; a1.w *= invA;
    b0.x *= invB; b0.y *= invB; b0.z *= invB; b0.w *= invB;
    b1.x *= invB; b1.y *= invB; b1.z *= invB; b1.w *= invB;

    ((float4*)rowA)[t]       = a0;
    ((float4*)rowA)[t + 256] = a1;
    ((float4*)rowB)[t]       = b0;
    ((float4*)rowB)[t + 256] = b1;

    {
        int c0 = i0 >> 2, cc = i0 & 3;
        if (c0 == t) {
            float d = (cc == 0) ? a0.x : (cc == 1) ? a0.y : (cc == 2) ? a0.z : a0.w;
            g_diag[rowg0] = d;
        } else if (c0 == t + 256) {
            float d = (cc == 0) ? a1.x : (cc == 1) ? a1.y : (cc == 2) ? a1.z : a1.w;
            g_diag[rowg0] = d;
        }
    }
    {
        int c0 = i1 >> 2, cc = i1 & 3;
        if (c0 == t) {
            float d = (cc == 0) ? b0.x : (cc == 1) ? b0.y : (cc == 2) ? b0.z : b0.w;
            g_diag[rowg0 + 1] = d;
        } else if (c0 == t + 256) {
            float d = (cc == 0) ? b1.x : (cc == 1) ? b1.y : (cc == 2) ? b1.z : b1.w;
            g_diag[rowg0 + 1] = d;
        }
    }
}

// ============================================================
// Kernel 3: FUSED rank counting + compaction.
// grid (128, BB), block 256; warp handles 2 elements via direct
// L2 reads (g_diag is 16KB, always resident). Last block per
// batch (atomic ticket) runs the deterministic block-scan
// compaction inline, then resets the ticket for graph replay.
// ============================================================
__global__ __launch_bounds__(256) void topk_fused_kernel()
{
    const int b = blockIdx.y;
    const float4* gd = (const float4*)(g_diag + b * NN);

    const int warp = threadIdx.x >> 5;
    const int lane = threadIdx.x & 31;
    const int ib = blockIdx.x * 16 + warp * 2;   // 2-aligned
    const int i4 = ib >> 2;
    const float vi0 = g_diag[b * NN + ib + 0];
    const float vi1 = g_diag[b * NN + ib + 1];

    int c0 = 0, c1 = 0;
#pragma unroll 4
    for (int j4 = lane; j4 < NN / 4; j4 += 32) {
        float4 w = __ldg(&gd[j4]);
        if (j4 < i4) {
            c0 += (w.x >= vi0) + (w.y >= vi0) + (w.z >= vi0) + (w.w >= vi0);
            c1 += (w.x >= vi1) + (w.y >= vi1) + (w.z >= vi1) + (w.w >= vi1);
        } else if (j4 > i4) {
            c0 += (w.x > vi0) + (w.y > vi0) + (w.z > vi0) + (w.w > vi0);
            c1 += (w.x > vi1) + (w.y > vi1) + (w.z > vi1) + (w.w > vi1);
        } else {
            int j = j4 * 4;
            c0 += ((w.x > vi0) || ((w.x == vi0) && (j + 0 < ib + 0)))
                + ((w.y > vi0) || ((w.y == vi0) && (j + 1 < ib + 0)))
                + ((w.z > vi0) || ((w.z == vi0) && (j + 2 < ib + 0)))
                + ((w.w > vi0) || ((w.w == vi0) && (j + 3 < ib + 0)));
            c1 += ((w.x > vi1) || ((w.x == vi1) && (j + 0 < ib + 1)))
                + ((w.y > vi1) || ((w.y == vi1) && (j + 1 < ib + 1)))
                + ((w.z > vi1) || ((w.z == vi1) && (j + 2 < ib + 1)))
                + ((w.w > vi1) || ((w.w == vi1) && (j + 3 < ib + 1)));
        }
    }
#pragma unroll
    for (int o = 16; o > 0; o >>= 1) {
        c0 += __shfl_xor_sync(0xffffffffu, c0, o);
        c1 += __shfl_xor_sync(0xffffffffu, c1, o);
    }

    if (lane == 0) {
        g_sel[b * NN + ib + 0] = (c0 < KK) ? 1 : 0;
        g_sel[b * NN + ib + 1] = (c1 < KK) ? 1 : 0;
    }

    // ---- last-block-done: compact inline ----
    __shared__ int s_last;
    __syncthreads();
    if (threadIdx.x == 0) {
        __threadfence();
        int tk = atomicAdd(&g_ticket[b], 1);
        s_last = (tk == gridDim.x - 1) ? 1 : 0;
    }
    __syncthreads();
    if (!s_last) return;

    // this block compacts: 256 threads x 8 flags each = 2048
    const int t = threadIdx.x;
    int f[8], mysum = 0;
#pragma unroll
    for (int e = 0; e < 8; e++) {
        f[e] = g_sel[b * NN + 8 * t + e];
        mysum += f[e];
    }

    __shared__ int wsum[8];
    int inc = mysum;
#pragma unroll
    for (int o = 1; o < 32; o <<= 1) {
        int u = __shfl_up_sync(0xffffffffu, inc, o);
        if ((t & 31) >= o) inc += u;
    }
    if ((t & 31) == 31) wsum[t >> 5] = inc;
    __syncthreads();
    int woff = 0;
#pragma unroll
    for (int w = 0; w < 8; w++) {
        if (w < (t >> 5)) woff += wsum[w];
    }

    int pos = woff + inc - mysum;     // exclusive prefix for flag 8t
#pragma unroll
    for (int e = 0; e < 8; e++) {
        if (f[e] && pos < KK) g_topidx[b * KK + pos] = 8 * t + e;
        pos += f[e];
    }

    if (t == 0) g_ticket[b] = 0;      // reset for next graph replay
}

// ============================================================
// Kernel 4: FUSED rel top-R + soi + LayerNorm(re).
// ============================================================
__global__ __launch_bounds__(160) void rel_re_kernel(
    const float* __restrict__ scores, const float* __restrict__ q,
    float* __restrict__ soi_out, float* __restrict__ re_out)
{
    const int b  = blockIdx.y;
    const int tI = blockIdx.x;
    __shared__ float r[KK];
    __shared__ unsigned char sel[KK];
    __shared__ int sobj[RR];

    const int ti = g_topidx[b * KK + tI];
    const int t  = threadIdx.x;

    if (t < KK) {
        int tj = g_topidx[b * KK + t];
        float val = scores[((size_t)b * NN + ti) * NN + tj];
        r[t] = (t == tI) ? BIGV : val;
    }
    __syncthreads();

    if (t < KK) {
        float vi = r[t];
        int cnt = 0;
#pragma unroll 4
        for (int j = 0; j < KK; j++) {
            float vj = r[j];
            cnt += (vj > vi) || ((vj == vi) && (j < t));
        }
        sel[t] = (cnt < RR) ? 1 : 0;
    }
    __syncthreads();

    if (t < KK && sel[t]) {
        int pos = 0;
#pragma unroll 4
        for (int j = 0; j < KK; j++) pos += (j < t) ? sel[j] : 0;
        if (pos < RR) {
            int obj = g_topidx[b * KK + t];
            sobj[pos] = obj;
            int p = (b * KK + tI) * RR + pos;
            size_t so = (size_t)p * 3;
            soi_out[so + 0] = (float)b;
            soi_out[so + 1] = (float)ti;
            soi_out[so + 2] = (float)obj;
        }
    }
    __syncthreads();

    const int w = t >> 5;
    const int lane = t & 31;
    const int obj = sobj[w];
    const float4* qs = (const float4*)(q + ((size_t)b * NN + ti)  * DD);
    const float4* qo = (const float4*)(q + ((size_t)b * NN + obj) * DD);

    float x[8];
    float s = 0.0f, s2 = 0.0f;
#pragma unroll
    for (int c = 0; c < 2; c++) {
        float4 a = qs[lane + 32 * c];
        float4 o = qo[lane + 32 * c];
        x[4 * c + 0] = a.x + o.x; x[4 * c + 1] = a.y + o.y;
        x[4 * c + 2] = a.z + o.z; x[4 * c + 3] = a.w + o.w;
    }
#pragma unroll
    for (int e = 0; e < 8; e++) { s += x[e]; s2 += x[e] * x[e]; }
#pragma unroll
    for (int o = 16; o > 0; o >>= 1) {
        s  += __shfl_xor_sync(0xffffffffu, s,  o);
        s2 += __shfl_xor_sync(0xffffffffu, s2, o);
    }
    const float mu  = s * (1.0f / DD);
    const float var = s2 * (1.0f / DD) - mu * mu;
    const float inv = rsqrtf(var + LN_EPS);

    const int p = (b * KK + tI) * RR + w;
    float4* dst = (float4*)(re_out + (size_t)p * DD);
#pragma unroll
    for (int c = 0; c < 2; c++) {
        float4 rr;
        rr.x = (x[4 * c + 0] - mu) * inv;
        rr.y = (x[4 * c + 1] - mu) * inv;
        rr.z = (x[4 * c + 2] - mu) * inv;
        rr.w = (x[4 * c + 3] - mu) * inv;
        dst[lane + 32 * c] = rr;
    }
}

// ============================================================
extern "C" void kernel_launch(void* const* d_in, const int* in_sizes, int n_in,
                              void* d_out, int out_size)
{
    const float* q = (const float*)d_in[0];
    const float* k = (const float*)d_in[1];

    float* scores = (float*)d_out;
    float* soi    = scores + (size_t)BB * NN * NN;
    float* re     = soi + (size_t)BB * KK * RR * 3;

    void *qs_ptr = nullptr, *ks_ptr = nullptr;
    cudaGetSymbolAddress(&qs_ptr, g_qsb);
    cudaGetSymbolAddress(&ks_ptr, g_ksb);

    cudaFuncSetAttribute(gemm_bf16k, cudaFuncAttributeMaxDynamicSharedMemorySize, SMEM_BYTES);

    split3b_kernel<<<dim3(BB * NN * DD / 8 / 256, 2), 256>>>(q, k);
    gemm_bf16k<<<dim3(NN / BN, NN / BM, BB), 256, SMEM_BYTES>>>(
        (const __nv_bfloat16*)qs_ptr, (const __nv_bfloat16*)ks_ptr, scores);
    softmax_kernel<<<BB * NN / 2, 256>>>(scores);
    topk_fused_kernel<<<dim3(NN / 16, BB), 256>>>();
    rel_re_kernel<<<dim3(KK, BB), 160>>>(scores, q, soi, re);
}